// round 14
// baseline (speedup 1.0000x reference)
#include <cuda_runtime.h>
#include <math.h>
#include <stdint.h>

#define BATCH   1024
#define NKPS    24
#define NEDGE   552
#define M_NODE  (BATCH*NKPS)    // 24576
#define M_EDGE  (BATCH*NEDGE)   // 565248
#define GE64    (M_EDGE/64)     // 8832
#define GN64    (M_NODE/64)     // 384
#define GN_BLK  (M_NODE/128)    // 192
#define BN_EPS  1e-5f

// ---------------- scratch (device globals) ---------------------------------
__device__ float g_bufA[(size_t)M_EDGE*128];   // h2 (x_skip), tf32-rounded
__device__ float g_n1 [(size_t)M_NODE*128];
__device__ float g_n2 [(size_t)M_NODE*128];
__device__ float g_n3 [(size_t)M_NODE*128];
__device__ float g_ps [(size_t)M_NODE*256];    // P|S per node, fp32
__device__ float g_pnode[(size_t)GE64*4*128];
__device__ float g_psfrag[2*16384];
__device__ float g_skipfrag[16384];
__device__ float g_w1f3[16384];
__device__ float g_l2m1[16384];
__device__ float g_l2m2[16384];
__device__ float g_l2m3[16384];
__device__ float g_l2m4[16384];
__device__ float g_beff[128];
__device__ float g_psum[(size_t)GE64*128];     // edge: channel-major [128][GE64]; node: block-major
__device__ float g_psq [(size_t)GE64*128];
__device__ float g_s[4*128];
__device__ float g_t[4*128];

// ---------------- helpers ----------------------------------------------------
__device__ __forceinline__ uint32_t smem_u32(const void* p) {
    uint32_t a;
    asm("{ .reg .u64 t; cvta.to.shared.u64 t, %1; cvt.u32.u64 %0, t; }" : "=r"(a) : "l"(p));
    return a;
}
__device__ __forceinline__ void cp16(uint32_t dst, const void* src) {
    asm volatile("cp.async.cg.shared.global [%0], [%1], 16;" :: "r"(dst), "l"(src));
}
__device__ __forceinline__ uint32_t f2tf(float x) {
    uint32_t u;
    asm("cvt.rna.tf32.f32 %0, %1;" : "=r"(u) : "f"(x));
    return u;
}
__device__ __forceinline__ float rtf(float x) { return __uint_as_float(f2tf(x)); }
__device__ __forceinline__ void mma8(float d[4],
                                     uint32_t a0, uint32_t a1, uint32_t a2, uint32_t a3,
                                     uint32_t b0, uint32_t b1) {
    asm volatile("mma.sync.aligned.m16n8k8.row.col.f32.tf32.tf32.f32 "
        "{%0,%1,%2,%3}, {%4,%5,%6,%7}, {%8,%9}, {%0,%1,%2,%3};"
        : "+f"(d[0]), "+f"(d[1]), "+f"(d[2]), "+f"(d[3])
        : "r"(a0), "r"(a1), "r"(a2), "r"(a3), "r"(b0), "r"(b1));
}

// =================== M=128 machinery (node-side kernels, occ 2) ===============
#define PAIR_BAR(wm) asm volatile("bar.sync %0, 64;" :: "r"(1 + (wm)) : "memory")
#define OFF_RECV   0
#define OFF_SEND   512
#define OFF_BE     1024
#define OFF_B2V    1536
#define OFF_ACH    2048     /* 2 x 10240 A chunk buffers [128][20] */
#define OFF_A2     22528    /* 128 x 132 floats = 67584 */
#define SMEM_TOTAL 90112

__device__ __forceinline__ void mma_frag_ldgW(float (&acc)[2][8][4],
        const uint32_t* As, int AST, const float* __restrict__ Wchunk,
        int wm, int wn, int lid)
{
    const int g = lid >> 2, tg = lid & 3;
    float4 w[8];
    const float4* wp = (const float4*)Wchunk + wn * 256 + lid;
#pragma unroll
    for (int nt = 0; nt < 8; nt++) w[nt] = __ldg(wp + nt * 32);
    uint32_t a[2][2][4];
#pragma unroll
    for (int f = 0; f < 2; f++) {
        const uint32_t* p = As + (wm * 32 + f * 16 + g) * AST + tg;
#pragma unroll
        for (int ks = 0; ks < 2; ks++) {
            a[f][ks][0] = p[ks * 8];
            a[f][ks][1] = p[8 * AST + ks * 8];
            a[f][ks][2] = p[ks * 8 + 4];
            a[f][ks][3] = p[8 * AST + ks * 8 + 4];
        }
    }
#pragma unroll
    for (int nt = 0; nt < 8; nt++) {
        uint32_t bx = __float_as_uint(w[nt].x), by = __float_as_uint(w[nt].y);
        uint32_t bz = __float_as_uint(w[nt].z), bw = __float_as_uint(w[nt].w);
        mma8(acc[0][nt], a[0][0][0], a[0][0][1], a[0][0][2], a[0][0][3], bx, by);
        mma8(acc[1][nt], a[1][0][0], a[1][0][1], a[1][0][2], a[1][0][3], bx, by);
        mma8(acc[0][nt], a[0][1][0], a[0][1][1], a[0][1][2], a[0][1][3], bz, bw);
        mma8(acc[1][nt], a[1][1][0], a[1][1][1], a[1][1][2], a[1][1][3], bz, bw);
    }
}
__device__ __forceinline__ void mma_frag_smemW(float (&acc)[2][8][4],
        const uint32_t* As, int AST, const float4* Wc, int wm, int wn, int lid)
{
    const int g = lid >> 2, tg = lid & 3;
    uint32_t a[2][2][4];
#pragma unroll
    for (int f = 0; f < 2; f++) {
        const uint32_t* p = As + (wm * 32 + f * 16 + g) * AST + tg;
#pragma unroll
        for (int ks = 0; ks < 2; ks++) {
            a[f][ks][0] = p[ks * 8];
            a[f][ks][1] = p[8 * AST + ks * 8];
            a[f][ks][2] = p[ks * 8 + 4];
            a[f][ks][3] = p[8 * AST + ks * 8 + 4];
        }
    }
    const float4* wp = Wc + wn * 256 + lid;
#pragma unroll
    for (int nt = 0; nt < 8; nt++) {
        float4 bv = wp[nt * 32];
        uint32_t bx = __float_as_uint(bv.x), by = __float_as_uint(bv.y);
        uint32_t bz = __float_as_uint(bv.z), bw = __float_as_uint(bv.w);
        mma8(acc[0][nt], a[0][0][0], a[0][0][1], a[0][0][2], a[0][0][3], bx, by);
        mma8(acc[1][nt], a[1][0][0], a[1][0][1], a[1][0][2], a[1][0][3], bx, by);
        mma8(acc[0][nt], a[0][1][0], a[0][1][1], a[0][1][2], a[0][1][3], bz, bw);
        mma8(acc[1][nt], a[1][1][0], a[1][1][1], a[1][1][2], a[1][1][3], bz, bw);
    }
}
__device__ __forceinline__ void issue_a_pair(int c, int buf, uint32_t sb, int pt, int wm,
                                             const float* Asrc, int row0) {
#pragma unroll
    for (int i = 0; i < 2; i++) {
        int idx4 = i * 64 + pt;
        int row = wm * 32 + (idx4 >> 2), c4 = idx4 & 3;
        cp16(sb + OFF_ACH + buf * 10240 + row * 80 + c4 * 16,
             Asrc + (size_t)(row0 + row) * 128 + c * 16 + c4 * 4);
    }
    asm volatile("cp.async.commit_group;");
}
__device__ __forceinline__ void layer_k128(float (&acc)[2][8][4], char* smem, uint32_t sb,
        const float* Asrc, int row0, const float* __restrict__ Wfrag,
        int wm, int wn, int lid, int pt, bool preissued)
{
    if (!preissued) {
        issue_a_pair(0, 0, sb, pt, wm, Asrc, row0);
        issue_a_pair(1, 1, sb, pt, wm, Asrc, row0);
    }
    for (int c = 0; c < 8; c++) {
        int buf = c & 1;
        if (c < 7) asm volatile("cp.async.wait_group 1;");
        else       asm volatile("cp.async.wait_group 0;");
        PAIR_BAR(wm);
        mma_frag_ldgW(acc, (const uint32_t*)(smem + OFF_ACH + buf * 10240), 20,
                      Wfrag + c * 2048, wm, wn, lid);
        PAIR_BAR(wm);
        if (c + 2 < 8) issue_a_pair(c + 2, buf, sb, pt, wm, Asrc, row0);
    }
}
__device__ __forceinline__ void layer2_direct(float (&acc)[2][8][4], char* smem,
        const float* __restrict__ Wfrag, int wm, int wn, int lid)
{
#pragma unroll
    for (int c = 0; c < 8; c++) {
        mma_frag_ldgW(acc, (const uint32_t*)(smem + OFF_A2) + c * 16, 132,
                      Wfrag + c * 2048, wm, wn, lid);
    }
}
template<bool ADDG>
__device__ __forceinline__ void epi1(float (&acc)[2][8][4], char* smem,
                                     int wm, int wn, int lid)
{
    float* A2 = (float*)(smem + OFF_A2);
    const float* be = (const float*)(smem + OFF_BE);
    const int g = lid >> 2, tg = lid & 3;
#pragma unroll
    for (int f = 0; f < 2; f++) {
        int r = wm * 32 + f * 16 + g;
#pragma unroll
        for (int nt = 0; nt < 8; nt++) {
            int n0 = wn * 64 + nt * 8 + tg * 2;
            float be0 = be[n0], be1 = be[n0 + 1];
            float g0x = 0.f, g0y = 0.f, g1x = 0.f, g1y = 0.f;
            if (ADDG) {
                float2 G0 = *(float2*)(A2 + r * 132 + n0);
                float2 G1 = *(float2*)(A2 + (r + 8) * 132 + n0);
                g0x = G0.x; g0y = G0.y; g1x = G1.x; g1y = G1.y;
            }
            float v0 = acc[f][nt][0] + be0 + g0x;
            float v1 = acc[f][nt][1] + be1 + g0y;
            float v2 = acc[f][nt][2] + be0 + g1x;
            float v3 = acc[f][nt][3] + be1 + g1y;
            v0 = (v0 > 0.f) ? v0 : expm1f(v0);
            v1 = (v1 > 0.f) ? v1 : expm1f(v1);
            v2 = (v2 > 0.f) ? v2 : expm1f(v2);
            v3 = (v3 > 0.f) ? v3 : expm1f(v3);
            *(float2*)(A2 + r * 132 + n0)       = make_float2(rtf(v0), rtf(v1));
            *(float2*)(A2 + (r + 8) * 132 + n0) = make_float2(rtf(v2), rtf(v3));
#pragma unroll
            for (int q = 0; q < 4; q++) acc[f][nt][q] = 0.f;
        }
    }
}
template<bool ROUND>
__device__ __forceinline__ void epi2(float (&acc)[2][8][4], char* smem,
                                     int wm, int wn, int lid)
{
    float* A2 = (float*)(smem + OFF_A2);
    const float* be = (const float*)(smem + OFF_B2V);
    const int g = lid >> 2, tg = lid & 3;
#pragma unroll
    for (int f = 0; f < 2; f++) {
        int r = wm * 32 + f * 16 + g;
#pragma unroll
        for (int nt = 0; nt < 8; nt++) {
            int n0 = wn * 64 + nt * 8 + tg * 2;
            float be0 = be[n0], be1 = be[n0 + 1];
            float v0 = acc[f][nt][0] + be0;
            float v1 = acc[f][nt][1] + be1;
            float v2 = acc[f][nt][2] + be0;
            float v3 = acc[f][nt][3] + be1;
            v0 = (v0 > 0.f) ? v0 : expm1f(v0);
            v1 = (v1 > 0.f) ? v1 : expm1f(v1);
            v2 = (v2 > 0.f) ? v2 : expm1f(v2);
            v3 = (v3 > 0.f) ? v3 : expm1f(v3);
            if (ROUND) { v0 = rtf(v0); v1 = rtf(v1); v2 = rtf(v2); v3 = rtf(v3); }
            *(float2*)(A2 + r * 132 + n0)       = make_float2(v0, v1);
            *(float2*)(A2 + (r + 8) * 132 + n0) = make_float2(v2, v3);
        }
    }
}
__device__ __forceinline__ void store_tile(char* smem, float* out, int row0, int tid,
                                           int ostride, int ocol)
{
    const float* A2 = (const float*)(smem + OFF_A2);
#pragma unroll
    for (int i = 0; i < 16; i++) {
        int idx4 = i * 256 + tid;
        int row = idx4 >> 5, c4 = idx4 & 31;
        float4 v = *(const float4*)(A2 + row * 132 + c4 * 4);
        *(float4*)(out + (size_t)(row0 + row) * ostride + ocol + c4 * 4) = v;
    }
}
__device__ __forceinline__ void stats_only(char* smem, int tid, int bx,
                                           float* psum, float* psq)
{
    if (tid >= 128) return;
    const float* A2 = (const float*)(smem + OFF_A2);
    float S = 0.f, Q = 0.f;
#pragma unroll 8
    for (int r = 0; r < 128; r++) {
        float x = A2[r * 132 + tid];
        S += x; Q += x * x;
    }
    psum[(size_t)bx * 128 + tid] = S;
    psq [(size_t)bx * 128 + tid] = Q;
}
#define ACC_DECL float acc[2][8][4]; \
    _Pragma("unroll") for (int f_ = 0; f_ < 2; f_++) \
    _Pragma("unroll") for (int n_ = 0; n_ < 8; n_++) \
    _Pragma("unroll") for (int q_ = 0; q_ < 4; q_++) acc[f_][n_][q_] = 0.f;

// =================== M=64 machinery (16x64 warp tiles, occ 4) =================
// 8 warps: wm = wid&3 (16-row m group), wn = wid>>2 (64-col n group).
#define PAIR_BAR64(wm) asm volatile("bar.sync %0, 64;" :: "r"(1 + (wm)) : "memory")
#define E_RECV   0
#define E_SEND   256
#define E_BE     512
#define E_B2V    1024
#define E_ACH    1536      /* 2 x 5120 A chunk buffers [64][20] */
#define E_A2     11776     /* 64 x 132 floats = 33792 */
#define E_SMEM   45568

__device__ __forceinline__ void mma_frag64(float (&acc)[8][4],
        const uint32_t* As, int AST, const float* __restrict__ Wchunk,
        int wm, int wn, int lid)
{
    const int g = lid >> 2, tg = lid & 3;
    uint32_t a[2][4];
    const uint32_t* p = As + (wm * 16 + g) * AST + tg;
#pragma unroll
    for (int ks = 0; ks < 2; ks++) {
        a[ks][0] = p[ks * 8];
        a[ks][1] = p[8 * AST + ks * 8];
        a[ks][2] = p[ks * 8 + 4];
        a[ks][3] = p[8 * AST + ks * 8 + 4];
    }
#pragma unroll
    for (int h = 0; h < 2; h++) {
        float4 w[4];
        const float4* wp = (const float4*)Wchunk + wn * 256 + h * 128 + lid;
#pragma unroll
        for (int i = 0; i < 4; i++) w[i] = __ldg(wp + i * 32);
#pragma unroll
        for (int i = 0; i < 4; i++) {
            int nt = h * 4 + i;
            uint32_t bx = __float_as_uint(w[i].x), by = __float_as_uint(w[i].y);
            uint32_t bz = __float_as_uint(w[i].z), bw = __float_as_uint(w[i].w);
            mma8(acc[nt], a[0][0], a[0][1], a[0][2], a[0][3], bx, by);
            mma8(acc[nt], a[1][0], a[1][1], a[1][2], a[1][3], bz, bw);
        }
    }
}
// pair = 2 warps sharing wm (64 threads), pt = wn*32+lid in 0..63; 1 cp16/thread
__device__ __forceinline__ void issue_a64(int c, int buf, uint32_t sb, int pt, int wm,
                                          const float* Asrc, int row0) {
    int row = wm * 16 + (pt >> 2), c4 = pt & 3;
    cp16(sb + E_ACH + buf * 5120 + row * 80 + c4 * 16,
         Asrc + (size_t)(row0 + row) * 128 + c * 16 + c4 * 4);
    asm volatile("cp.async.commit_group;");
}
__device__ __forceinline__ void layer1_64(float (&acc)[8][4], char* smem, uint32_t sb,
        const float* Asrc, int row0, const float* __restrict__ Wfrag,
        int wm, int wn, int lid, int pt, bool preissued)
{
    if (!preissued) {
        issue_a64(0, 0, sb, pt, wm, Asrc, row0);
        issue_a64(1, 1, sb, pt, wm, Asrc, row0);
    }
    for (int c = 0; c < 8; c++) {
        int buf = c & 1;
        if (c < 7) asm volatile("cp.async.wait_group 1;");
        else       asm volatile("cp.async.wait_group 0;");
        PAIR_BAR64(wm);
        mma_frag64(acc, (const uint32_t*)(smem + E_ACH + buf * 5120), 20,
                   Wfrag + c * 2048, wm, wn, lid);
        PAIR_BAR64(wm);
        if (c + 2 < 8) issue_a64(c + 2, buf, sb, pt, wm, Asrc, row0);
    }
}
__device__ __forceinline__ void layer2_64(float (&acc)[8][4], char* smem,
        const float* __restrict__ Wfrag, int wm, int wn, int lid)
{
#pragma unroll
    for (int c = 0; c < 8; c++) {
        mma_frag64(acc, (const uint32_t*)(smem + E_A2) + c * 16, 132,
                   Wfrag + c * 2048, wm, wn, lid);
    }
}
template<bool ADDG>
__device__ __forceinline__ void epi1_64(float (&acc)[8][4], char* smem,
                                        int wm, int wn, int lid)
{
    float* A2 = (float*)(smem + E_A2);
    const float* be = (const float*)(smem + E_BE);
    const int g = lid >> 2, tg = lid & 3;
    int r = wm * 16 + g;
#pragma unroll
    for (int nt = 0; nt < 8; nt++) {
        int n0 = wn * 64 + nt * 8 + tg * 2;
        float be0 = be[n0], be1 = be[n0 + 1];
        float g0x = 0.f, g0y = 0.f, g1x = 0.f, g1y = 0.f;
        if (ADDG) {
            float2 G0 = *(float2*)(A2 + r * 132 + n0);
            float2 G1 = *(float2*)(A2 + (r + 8) * 132 + n0);
            g0x = G0.x; g0y = G0.y; g1x = G1.x; g1y = G1.y;
        }
        float v0 = acc[nt][0] + be0 + g0x;
        float v1 = acc[nt][1] + be1 + g0y;
        float v2 = acc[nt][2] + be0 + g1x;
        float v3 = acc[nt][3] + be1 + g1y;
        v0 = (v0 > 0.f) ? v0 : expm1f(v0);
        v1 = (v1 > 0.f) ? v1 : expm1f(v1);
        v2 = (v2 > 0.f) ? v2 : expm1f(v2);
        v3 = (v3 > 0.f) ? v3 : expm1f(v3);
        *(float2*)(A2 + r * 132 + n0)       = make_float2(rtf(v0), rtf(v1));
        *(float2*)(A2 + (r + 8) * 132 + n0) = make_float2(rtf(v2), rtf(v3));
#pragma unroll
        for (int q = 0; q < 4; q++) acc[nt][q] = 0.f;
    }
}
template<bool ROUND>
__device__ __forceinline__ void epi2_64(float (&acc)[8][4], char* smem,
                                        int wm, int wn, int lid)
{
    float* A2 = (float*)(smem + E_A2);
    const float* be = (const float*)(smem + E_B2V);
    const int g = lid >> 2, tg = lid & 3;
    int r = wm * 16 + g;
#pragma unroll
    for (int nt = 0; nt < 8; nt++) {
        int n0 = wn * 64 + nt * 8 + tg * 2;
        float be0 = be[n0], be1 = be[n0 + 1];
        float v0 = acc[nt][0] + be0;
        float v1 = acc[nt][1] + be1;
        float v2 = acc[nt][2] + be0;
        float v3 = acc[nt][3] + be1;
        v0 = (v0 > 0.f) ? v0 : expm1f(v0);
        v1 = (v1 > 0.f) ? v1 : expm1f(v1);
        v2 = (v2 > 0.f) ? v2 : expm1f(v2);
        v3 = (v3 > 0.f) ? v3 : expm1f(v3);
        if (ROUND) { v0 = rtf(v0); v1 = rtf(v1); v2 = rtf(v2); v3 = rtf(v3); }
        *(float2*)(A2 + r * 132 + n0)       = make_float2(v0, v1);
        *(float2*)(A2 + (r + 8) * 132 + n0) = make_float2(v2, v3);
    }
}
__device__ __forceinline__ void store_tile64(char* smem, float* out, int row0, int tid,
                                             int ostride, int ocol)
{
    const float* A2 = (const float*)(smem + E_A2);
#pragma unroll
    for (int i = 0; i < 8; i++) {
        int idx4 = i * 256 + tid;
        int row = idx4 >> 5, c4 = idx4 & 31;
        float4 v = *(const float4*)(A2 + row * 132 + c4 * 4);
        *(float4*)(out + (size_t)(row0 + row) * ostride + ocol + c4 * 4) = v;
    }
}
__device__ __forceinline__ void stats64(char* smem, int row0, int tid, int bx,
        float* psum, float* psq, float* pnode)
{
    if (tid >= 128) return;
    const float* A2 = (const float*)(smem + E_A2);
    float S = 0.f, Q = 0.f, nacc = 0.f;
    int slot = 0;
    int nxt = 23 - (row0 % 23);
    float* pb = pnode + (size_t)bx * 4 * 128;
#pragma unroll 4
    for (int r = 0; r < 64; r++) {
        if (r == nxt) { pb[slot * 128 + tid] = nacc; slot++; nacc = 0.f; nxt += 23; }
        float x = A2[r * 132 + tid];
        S += x; Q += x * x; nacc += x;
    }
    pb[slot * 128 + tid] = nacc;
    psum[(size_t)tid * GE64 + bx] = S;
    psq [(size_t)tid * GE64 + bx] = Q;
}
__device__ __forceinline__ void fill_edges64(char* smem, int row0, int tid) {
    if (tid < 64) {
        int row = row0 + tid;
        int b = row / NEDGE;
        int e = row - b * NEDGE;
        int r = e / 23;
        int j = e - r * 23;
        int s = j + (j >= r);
        ((int*)(smem + E_RECV))[tid] = b * NKPS + r;
        ((int*)(smem + E_SEND))[tid] = b * NKPS + s;
    }
}
#define ACC64_DECL float acc[8][4]; \
    _Pragma("unroll") for (int n_ = 0; n_ < 8; n_++) \
    _Pragma("unroll") for (int q_ = 0; q_ < 4; q_++) acc[n_][q_] = 0.f;

// =================== kernels ==================================================
__global__ __launch_bounds__(256, 2)
void stage1_mlp(const float* __restrict__ X, const float* __restrict__ W1,
                const float* __restrict__ b1, const float* __restrict__ W2frag,
                const float* __restrict__ b2, float* __restrict__ out,
                float* __restrict__ psum, float* __restrict__ psq)
{
    extern __shared__ char smem[];
    const int tid = threadIdx.x, wid = tid >> 5, lid = tid & 31;
    const int wm = wid & 3, wn = wid >> 2;
    const int row0 = blockIdx.x * 128;
    float* smf = (float*)smem;
    if (tid < 128) { smf[OFF_BE/4 + tid] = b1[tid]; smf[OFF_B2V/4 + tid] = b2[tid]; }
#pragma unroll
    for (int i = 0; i < 8; i++) {
        int idx = i * 256 + tid;
        int row = idx >> 4, col = idx & 15;
        float av = (col < 6) ? X[(size_t)(row0 + row) * 6 + col] : 0.f;
        smf[OFF_ACH/4 + row * 20 + col] = rtf(av);
    }
#pragma unroll
    for (int i = 0; i < 8; i++) {
        int o = i * 256 + tid;
        int f4 = o >> 2, reg = o & 3;
        int nb = f4 >> 5, lane = f4 & 31, gg = lane >> 2, tg = lane & 3;
        int n = nb * 8 + gg;
        int k = (reg >> 1) * 8 + (reg & 1) * 4 + tg;
        smf[(OFF_ACH + 10240)/4 + o] = rtf((k < 6) ? W1[n * 6 + k] : 0.f);
    }
    __syncthreads();
    ACC_DECL
    mma_frag_smemW(acc, (const uint32_t*)(smem + OFF_ACH), 20,
                   (const float4*)(smem + OFF_ACH + 10240), wm, wn, lid);
    epi1<false>(acc, smem, wm, wn, lid);
    __syncthreads();
    layer2_direct(acc, smem, W2frag, wm, wn, lid);
    epi2<true>(acc, smem, wm, wn, lid);
    __syncthreads();
    store_tile(smem, out, row0, tid, 128, 0);
    stats_only(smem, tid, blockIdx.x, psum, psq);
}

__global__ __launch_bounds__(256, 2)
void node_mlp(const float* __restrict__ A, const float* __restrict__ W1frag,
              const float* __restrict__ b1, const float* __restrict__ W2frag,
              const float* __restrict__ b2, float* __restrict__ out,
              float* __restrict__ psum, float* __restrict__ psq)
{
    extern __shared__ char smem[];
    const uint32_t sb = smem_u32(smem);
    const int tid = threadIdx.x, wid = tid >> 5, lid = tid & 31;
    const int wm = wid & 3, wn = wid >> 2;
    const int pt = lid + wn * 32;
    const int row0 = blockIdx.x * 128;
    float* smf = (float*)smem;
    if (tid < 128) { smf[OFF_BE/4 + tid] = b1[tid]; smf[OFF_B2V/4 + tid] = b2[tid]; }
    __syncthreads();
    ACC_DECL
    layer_k128(acc, smem, sb, A, row0, W1frag, wm, wn, lid, pt, false);
    epi1<false>(acc, smem, wm, wn, lid);
    __syncthreads();
    layer2_direct(acc, smem, W2frag, wm, wn, lid);
    epi2<true>(acc, smem, wm, wn, lid);
    __syncthreads();
    store_tile(smem, out, row0, tid, 128, 0);
    stats_only(smem, tid, blockIdx.x, psum, psq);
}

// PS[:, blk*128 : +128] = A @ Wfrag(blk)^T, raw fp32  (M=64, 16x64 tiles, occ 4)
__global__ __launch_bounds__(256, 4)
void gemm_node(const float* __restrict__ A, const float* __restrict__ Wfrag,
               float* __restrict__ PS)
{
    extern __shared__ char smem[];
    const uint32_t sb = smem_u32(smem);
    const int tid = threadIdx.x, wid = tid >> 5, lid = tid & 31;
    const int wm = wid & 3, wn = wid >> 2;
    const int pt = wn * 32 + lid;
    const int row0 = blockIdx.x * 64;
    const int blk = blockIdx.y;
    ACC64_DECL
    layer1_64(acc, smem, sb, A, row0, Wfrag + (size_t)blk * 16384, wm, wn, lid, pt, false);
    float* A2 = (float*)(smem + E_A2);
    const int g = lid >> 2, tg = lid & 3;
    int r = wm * 16 + g;
#pragma unroll
    for (int nt = 0; nt < 8; nt++) {
        int n0 = wn * 64 + nt * 8 + tg * 2;
        *(float2*)(A2 + r * 132 + n0)       = make_float2(acc[nt][0], acc[nt][1]);
        *(float2*)(A2 + (r + 8) * 132 + n0) = make_float2(acc[nt][2], acc[nt][3]);
    }
    __syncthreads();
    store_tile64(smem, PS, row0, tid, 256, blk * 128);
}

// stage 2 edges (M=64, occ 4)
__global__ __launch_bounds__(256, 4)
void edge_stage2(const float* __restrict__ PS, const float* __restrict__ beff,
                 const float* __restrict__ W2frag, const float* __restrict__ b2,
                 float* __restrict__ out, float* __restrict__ psum, float* __restrict__ psq,
                 float* __restrict__ pnode)
{
    extern __shared__ char smem[];
    const int tid = threadIdx.x, wid = tid >> 5, lid = tid & 31;
    const int wm = wid & 3, wn = wid >> 2;
    const int row0 = blockIdx.x * 64;
    float* smf = (float*)smem;
    fill_edges64(smem, row0, tid);
    if (tid < 128) { smf[E_BE/4 + tid] = beff[tid]; smf[E_B2V/4 + tid] = b2[tid]; }
    __syncthreads();
    const int* rs = (const int*)(smem + E_RECV);
    const int* ss = (const int*)(smem + E_SEND);
    float* A2 = (float*)(smem + E_A2);
    const float* be = smf + E_BE/4;
#pragma unroll
    for (int i = 0; i < 8; i++) {
        int idx4 = i * 256 + tid;
        int row = idx4 >> 5, c4 = idx4 & 31;
        float4 p = *(const float4*)(PS + (size_t)rs[row] * 256 + c4 * 4);
        float4 s = *(const float4*)(PS + (size_t)ss[row] * 256 + 128 + c4 * 4);
        float v0 = p.x + s.x + be[c4 * 4];
        float v1 = p.y + s.y + be[c4 * 4 + 1];
        float v2 = p.z + s.z + be[c4 * 4 + 2];
        float v3 = p.w + s.w + be[c4 * 4 + 3];
        v0 = (v0 > 0.f) ? v0 : expm1f(v0);
        v1 = (v1 > 0.f) ? v1 : expm1f(v1);
        v2 = (v2 > 0.f) ? v2 : expm1f(v2);
        v3 = (v3 > 0.f) ? v3 : expm1f(v3);
        *(float4*)(A2 + row * 132 + c4 * 4) = make_float4(rtf(v0), rtf(v1), rtf(v2), rtf(v3));
    }
    __syncthreads();
    ACC64_DECL
    layer2_64(acc, smem, W2frag, wm, wn, lid);
    epi2_64<true>(acc, smem, wm, wn, lid);
    __syncthreads();
    store_tile64(smem, out, row0, tid, 128, 0);
    stats64(smem, row0, tid, blockIdx.x, psum, psq, pnode);
}

// stage 4 edges (M=64, occ 4)
__global__ __launch_bounds__(256, 4)
void edge_stage4(const float* __restrict__ PS3, const float* __restrict__ H2,
                 const float* __restrict__ SKIPfrag, const float* __restrict__ beff,
                 const float* __restrict__ W2frag, const float* __restrict__ b2,
                 float* __restrict__ psum, float* __restrict__ psq,
                 float* __restrict__ pnode)
{
    extern __shared__ char smem[];
    const uint32_t sb = smem_u32(smem);
    const int tid = threadIdx.x, wid = tid >> 5, lid = tid & 31;
    const int wm = wid & 3, wn = wid >> 2;
    const int pt = wn * 32 + lid;
    const int row0 = blockIdx.x * 64;
    float* smf = (float*)smem;
    fill_edges64(smem, row0, tid);
    if (tid < 128) { smf[E_BE/4 + tid] = beff[tid]; smf[E_B2V/4 + tid] = b2[tid]; }
    issue_a64(0, 0, sb, pt, wm, H2, row0);
    issue_a64(1, 1, sb, pt, wm, H2, row0);
    __syncthreads();
    const int* rs = (const int*)(smem + E_RECV);
    const int* ss = (const int*)(smem + E_SEND);
    float* A2 = (float*)(smem + E_A2);
#pragma unroll
    for (int i = 0; i < 8; i++) {
        int idx4 = i * 256 + tid;
        int row = idx4 >> 5, c4 = idx4 & 31;
        float4 p = *(const float4*)(PS3 + (size_t)rs[row] * 256 + c4 * 4);
        float4 s = *(const float4*)(PS3 + (size_t)ss[row] * 256 + 128 + c4 * 4);
        *(float4*)(A2 + row * 132 + c4 * 4) =
            make_float4(p.x + s.x, p.y + s.y, p.z + s.z, p.w + s.w);
    }
    ACC64_DECL
    layer1_64(acc, smem, sb, H2, row0, SKIPfrag, wm, wn, lid, pt, true);
    epi1_64<true>(acc, smem, wm, wn, lid);
    __syncthreads();
    layer2_64(acc, smem, W2frag, wm, wn, lid);
    epi2_64<false>(acc, smem, wm, wn, lid);
    __syncthreads();
    stats64(smem, row0, tid, blockIdx.x, psum, psq, pnode);
}

// combine node partials (stage-2 path): 64-row blocks
__global__ void node_combine(const float* __restrict__ pnode,
                             const float* __restrict__ s, const float* __restrict__ t,
                             float* __restrict__ outn)
{
    int idx = blockIdx.x * 256 + threadIdx.x;
    int n = idx >> 7, c = idx & 127;
    int e0 = n * 23, e1 = e0 + 22;
    int b0 = e0 >> 6, b1 = e1 >> 6;
    int s0 = n - (b0 * 64) / 23;
    float sum = pnode[((size_t)b0 * 4 + s0) * 128 + c];
    if (b1 != b0) {
        int s1 = n - (b1 * 64) / 23;
        sum += pnode[((size_t)b1 * 4 + s1) * 128 + c];
    }
    outn[(size_t)n * 128 + c] = rtf((s[c] * sum + 23.f * t[c]) * (1.f / 24.f));
}

// ---- preps --------------------------------------------------------------------
__device__ __forceinline__ void frag_block(const float* W, int Kin, int kofs,
                                           const float* sv, float* dst, int o)
{
    int c = o >> 11, rem = o & 2047;
    int f4 = rem >> 2, reg = rem & 3;
    int nb = f4 >> 5, lane = f4 & 31;
    int g = lane >> 2, tg = lane & 3;
    int n = nb * 8 + g;
    int k = c * 16 + (reg >> 1) * 8 + (reg & 1) * 4 + tg;
    float v = W[(size_t)n * Kin + kofs + k];
    if (sv) v *= sv[k];
    dst[o] = __uint_as_float(f2tf(v));
}
__device__ __forceinline__ void bias_block(const float* W, int Kin, const float* b,
                                           const float* ta, const float* tb,
                                           float* beff, int n, int tid)
{
    float partial = 0.f;
    for (int k = tid; k < Kin; k += 256) {
        float t = (k < 256) ? ta[k & 127] : tb[k - 256];
        partial += W[(size_t)n * Kin + k] * t;
    }
    __shared__ float red[256];
    red[tid] = partial;
    __syncthreads();
    for (int off = 128; off; off >>= 1) {
        if (tid < off) red[tid] += red[tid + off];
        __syncthreads();
    }
    if (tid == 0) beff[n] = b[n] + red[0];
}
__device__ __forceinline__ void bn_inline(const float* psum, const float* psq,
                                          float Minv, const float* g, const float* be,
                                          float* ss, float* st, int tid)
{
    if (tid < 128) {
        float S = 0.f, Q = 0.f;
        for (int i = 0; i < GN_BLK; i++) {
            S += psum[i * 128 + tid];
            Q += psq [i * 128 + tid];
        }
        float mean = S * Minv;
        float var  = Q * Minv - mean * mean;
        float inv  = rsqrtf(var + BN_EPS);
        float sv   = g[tid] * inv;
        ss[tid] = sv;
        st[tid] = be[tid] - mean * sv;
    }
    __syncthreads();
}

__global__ void prep_indep(const float* W0, const float* W1, const float* W2,
                           const float* W3, const float* W4,
                           float* D0, float* D1, float* D2, float* D3, float* D4)
{
    int sel = blockIdx.x >> 6;
    int o = (blockIdx.x & 63) * 256 + threadIdx.x;
    const float* W = (sel == 0) ? W0 : (sel == 1) ? W1 : (sel == 2) ? W2
                   : (sel == 3) ? W3 : W4;
    float* D = (sel == 0) ? D0 : (sel == 1) ? D1 : (sel == 2) ? D2
             : (sel == 3) ? D3 : D4;
    frag_block(W, 128, 0, nullptr, D, o);
}
__global__ void prep_stage2(const float* __restrict__ W1, const float* __restrict__ b1,
                            const float* __restrict__ psum, const float* __restrict__ psq,
                            float Minv, const float* __restrict__ gg,
                            const float* __restrict__ gb,
                            float* __restrict__ psfrag, float* __restrict__ beff)
{
    __shared__ float ss[128], st[128];
    int bx = blockIdx.x, tid = threadIdx.x;
    bn_inline(psum, psq, Minv, gg, gb, ss, st, tid);
    if (bx < 64)        frag_block(W1, 256, 0,   ss, psfrag,          bx * 256 + tid);
    else if (bx < 128)  frag_block(W1, 256, 128, ss, psfrag + 16384,  (bx - 64) * 256 + tid);
    else                bias_block(W1, 256, b1, st, nullptr, beff, bx - 128, tid);
}
__global__ void prep_stage4(const float* __restrict__ W1, const float* __restrict__ b1,
                            const float* __restrict__ psum, const float* __restrict__ psq,
                            float Minv, const float* __restrict__ gg,
                            const float* __restrict__ gb,
                            const float* __restrict__ s2, const float* __restrict__ t2,
                            float* __restrict__ psfrag, float* __restrict__ skipfrag,
                            float* __restrict__ beff)
{
    __shared__ float ss[128], st[128];
    int bx = blockIdx.x, tid = threadIdx.x;
    bn_inline(psum, psq, Minv, gg, gb, ss, st, tid);
    if (bx < 64)        frag_block(W1, 384, 0,   ss, psfrag,          bx * 256 + tid);
    else if (bx < 128)  frag_block(W1, 384, 128, ss, psfrag + 16384,  (bx - 64) * 256 + tid);
    else if (bx < 192)  frag_block(W1, 384, 256, s2, skipfrag,        (bx - 128) * 256 + tid);
    else                bias_block(W1, 384, b1, st, t2, beff, bx - 192, tid);
}

__global__ void bn_edge(const float* __restrict__ psum, const float* __restrict__ psq,
                        float Minv, const float* __restrict__ g, const float* __restrict__ be,
                        float* __restrict__ s, float* __restrict__ t)
{
    const int c = blockIdx.x, tid = threadIdx.x;
    float S = 0.f, Q = 0.f;
    for (int i = tid; i < GE64; i += 256) {
        S += psum[(size_t)c * GE64 + i];
        Q += psq [(size_t)c * GE64 + i];
    }
    __shared__ float rs[256], rq[256];
    rs[tid] = S; rq[tid] = Q;
    __syncthreads();
    for (int off = 128; off; off >>= 1) {
        if (tid < off) { rs[tid] += rs[tid + off]; rq[tid] += rq[tid + off]; }
        __syncthreads();
    }
    if (tid == 0) {
        float mean = rs[0] * Minv;
        float var  = rq[0] * Minv - mean * mean;
        float inv  = rsqrtf(var + BN_EPS);
        float sv   = g[c] * inv;
        s[c] = sv;
        t[c] = be[c] - mean * sv;
    }
}

__global__ void final_proj(const float* __restrict__ pnode,
                           const float* __restrict__ s, const float* __restrict__ t,
                           const float* __restrict__ fo_w, const float* __restrict__ fo_b,
                           float* __restrict__ out)
{
    int b = blockIdx.x;
    int c = threadIdx.x;
    float sc = s[c], tc = t[c];
    float a0 = 0.f, a1 = 0.f;
#pragma unroll
    for (int n = 0; n < NKPS; n++) {
        int nn = b * NKPS + n;
        int e0 = nn * 23, e1 = e0 + 22;
        int b0 = e0 >> 6, b1e = e1 >> 6;
        int s0 = nn - (b0 * 64) / 23;
        float sum = pnode[((size_t)b0 * 4 + s0) * 128 + c];
        if (b1e != b0) {
            int s1 = nn - (b1e * 64) / 23;
            sum += pnode[((size_t)b1e * 4 + s1) * 128 + c];
        }
        float v = (sc * sum + 23.f * tc) * (1.f / 24.f);
        a0 = fmaf(v, fo_w[n * 128 + c],        a0);
        a1 = fmaf(v, fo_w[3072 + n * 128 + c], a1);
    }
    __shared__ float r0[128], r1[128];
    r0[c] = a0; r1[c] = a1;
    __syncthreads();
    for (int off = 64; off; off >>= 1) {
        if (c < off) { r0[c] += r0[c + off]; r1[c] += r1[c + off]; }
        __syncthreads();
    }
    if (c == 0) {
        out[b * 2 + 0] = r0[0] + fo_b[0];
        out[b * 2 + 1] = r1[0] + fo_b[1];
    }
}

// ---- launch -------------------------------------------------------------------
extern "C" void kernel_launch(void* const* d_in, const int* in_sizes, int n_in,
                              void* d_out, int out_size)
{
    const float** I = (const float**)d_in;
    const float* inputs = I[0];
    const float *fo_w = I[3], *fo_b = I[4];
    const float *m1w1 = I[5],  *m1b1 = I[6],  *m1w2 = I[7],  *m1b2 = I[8],  *m1g = I[9],  *m1be = I[10];
    const float *m2w1 = I[11], *m2b1 = I[12], *m2w2 = I[13], *m2b2 = I[14], *m2g = I[15], *m2be = I[16];
    const float *m3w1 = I[17], *m3b1 = I[18], *m3w2 = I[19], *m3b2 = I[20], *m3g = I[21], *m3be = I[22];
    const float *m4w1 = I[23], *m4b1 = I[24], *m4w2 = I[25], *m4b2 = I[26], *m4g = I[27], *m4be = I[28];
    float* out = (float*)d_out;

    float *bufA, *n1, *n2, *n3, *ps, *pnode, *psfrag, *skipfrag, *w1f3;
    float *l2m1, *l2m2, *l2m3, *l2m4;
    float *beff, *psum, *psq, *sA, *tA;
    cudaGetSymbolAddress((void**)&bufA, g_bufA);
    cudaGetSymbolAddress((void**)&n1, g_n1);
    cudaGetSymbolAddress((void**)&n2, g_n2);
    cudaGetSymbolAddress((void**)&n3, g_n3);
    cudaGetSymbolAddress((void**)&ps, g_ps);
    cudaGetSymbolAddress((void**)&pnode, g_pnode);
    cudaGetSymbolAddress((void**)&psfrag, g_psfrag);
    cudaGetSymbolAddress((void**)&skipfrag, g_skipfrag);
    cudaGetSymbolAddress((void**)&w1f3, g_w1f3);
    cudaGetSymbolAddress((void**)&l2m1, g_l2m1);
    cudaGetSymbolAddress((void**)&l2m2, g_l2m2);
    cudaGetSymbolAddress((void**)&l2m3, g_l2m3);
    cudaGetSymbolAddress((void**)&l2m4, g_l2m4);
    cudaGetSymbolAddress((void**)&beff, g_beff);
    cudaGetSymbolAddress((void**)&psum, g_psum);
    cudaGetSymbolAddress((void**)&psq, g_psq);
    cudaGetSymbolAddress((void**)&sA, g_s);
    cudaGetSymbolAddress((void**)&tA, g_t);

    cudaFuncSetAttribute(stage1_mlp,  cudaFuncAttributeMaxDynamicSharedMemorySize, SMEM_TOTAL);
    cudaFuncSetAttribute(node_mlp,    cudaFuncAttributeMaxDynamicSharedMemorySize, SMEM_TOTAL);
    cudaFuncSetAttribute(gemm_node,   cudaFuncAttributeMaxDynamicSharedMemorySize, E_SMEM);
    cudaFuncSetAttribute(edge_stage2, cudaFuncAttributeMaxDynamicSharedMemorySize, E_SMEM);
    cudaFuncSetAttribute(edge_stage4, cudaFuncAttributeMaxDynamicSharedMemorySize, E_SMEM);

    const float MinvN = 1.0f / (float)M_NODE;
    const float MinvE = 1.0f / (float)M_EDGE;
    dim3 gnode(GN64, 2);

    // #1: all scale-independent weight frags
    prep_indep<<<320, 256>>>(m1w2, m2w2, m3w1, m3w2, m4w2,
                             l2m1, l2m2, w1f3, l2m3, l2m4);
    // #2: stage 1 (M=128)
    stage1_mlp<<<GN_BLK, 256, SMEM_TOTAL>>>(inputs, m1w1, m1b1, l2m1, m1b2, n1, psum, psq);
    // #3: stage-2 prep (BN1 fused)
    prep_stage2<<<256, 256>>>(m2w1, m2b1, psum, psq, MinvN, m1g, m1be, psfrag, beff);
    // #4: node P/S GEMM (M=64, occ 4)  <-- profiled launch
    gemm_node<<<gnode, 256, E_SMEM>>>(n1, psfrag, ps);
    // #5: edges stage 2 (M=64, occ 4)
    edge_stage2<<<GE64, 256, E_SMEM>>>(ps, beff, l2m2, m2b2, bufA, psum, psq, pnode);
    // #6: BN2
    bn_edge<<<128, 256>>>(psum, psq, MinvE, m2g, m2be, sA + 128, tA + 128);
    // #7: edge2node
    node_combine<<<M_NODE * 128 / 256, 256>>>(pnode, sA + 128, tA + 128, n2);
    // #8: stage 3 (M=128)
    node_mlp<<<GN_BLK, 256, SMEM_TOTAL>>>(n2, w1f3, m3b1, l2m3, m3b2, n3, psum, psq);
    // #9: stage-4 prep (BN3 fused)
    prep_stage4<<<320, 256>>>(m4w1, m4b1, psum, psq, MinvN, m3g, m3be,
                              sA + 128, tA + 128, psfrag, skipfrag, beff);
    // #10: node P/S GEMM for stage 4
    gemm_node<<<gnode, 256, E_SMEM>>>(n3, psfrag, ps);
    // #11: edges stage 4 (M=64, occ 4)
    edge_stage4<<<GE64, 256, E_SMEM>>>(ps, bufA, skipfrag, beff, l2m4, m4b2, psum, psq, pnode);
    // #12: BN4
    bn_edge<<<128, 256>>>(psum, psq, MinvE, m4g, m4be, sA + 384, tA + 384);
    // #13: final projection with fused combine
    final_proj<<<BATCH, 128>>>(pnode, sA + 384, tA + 384, fo_w, fo_b, out);
}

// round 15
// speedup vs baseline: 1.0385x; 1.0385x over previous
#include <cuda_runtime.h>
#include <math.h>
#include <stdint.h>

#define BATCH   1024
#define NKPS    24
#define NEDGE   552
#define M_NODE  (BATCH*NKPS)    // 24576
#define M_EDGE  (BATCH*NEDGE)   // 565248
#define GE64    (M_EDGE/64)     // 8832
#define GN64    (M_NODE/64)     // 384
#define GN_BLK  (M_NODE/128)    // 192
#define BN_EPS  1e-5f

// ---------------- scratch (device globals) ---------------------------------
__device__ float g_bufA[(size_t)M_EDGE*128];   // h2 (x_skip), tf32-rounded
__device__ float g_n1 [(size_t)M_NODE*128];
__device__ float g_n2 [(size_t)M_NODE*128];
__device__ float g_n3 [(size_t)M_NODE*128];
__device__ float g_ps [(size_t)M_NODE*256];    // P|S per node, fp32
__device__ float g_pnode[(size_t)GE64*4*128];
__device__ float g_psfrag[2*16384];
__device__ float g_skipfrag[16384];
__device__ float g_w1f3[16384];
__device__ float g_l2m1[16384];
__device__ float g_l2m2[16384];
__device__ float g_l2m3[16384];
__device__ float g_l2m4[16384];
__device__ float g_beff[128];
__device__ float g_psum[(size_t)GE64*128];     // edge: channel-major [128][GE64]; node: block-major
__device__ float g_psq [(size_t)GE64*128];
__device__ float g_s[4*128];
__device__ float g_t[4*128];

// ---------------- helpers ----------------------------------------------------
__device__ __forceinline__ uint32_t smem_u32(const void* p) {
    uint32_t a;
    asm("{ .reg .u64 t; cvta.to.shared.u64 t, %1; cvt.u32.u64 %0, t; }" : "=r"(a) : "l"(p));
    return a;
}
__device__ __forceinline__ void cp16(uint32_t dst, const void* src) {
    asm volatile("cp.async.cg.shared.global [%0], [%1], 16;" :: "r"(dst), "l"(src));
}
__device__ __forceinline__ uint32_t f2tf(float x) {
    uint32_t u;
    asm("cvt.rna.tf32.f32 %0, %1;" : "=r"(u) : "f"(x));
    return u;
}
__device__ __forceinline__ float rtf(float x) { return __uint_as_float(f2tf(x)); }
__device__ __forceinline__ void mma8(float d[4],
                                     uint32_t a0, uint32_t a1, uint32_t a2, uint32_t a3,
                                     uint32_t b0, uint32_t b1) {
    asm volatile("mma.sync.aligned.m16n8k8.row.col.f32.tf32.tf32.f32 "
        "{%0,%1,%2,%3}, {%4,%5,%6,%7}, {%8,%9}, {%0,%1,%2,%3};"
        : "+f"(d[0]), "+f"(d[1]), "+f"(d[2]), "+f"(d[3])
        : "r"(a0), "r"(a1), "r"(a2), "r"(a3), "r"(b0), "r"(b1));
}

// =================== M=128 machinery (stage-1 kernel, occ 2) ==================
#define PAIR_BAR(wm) asm volatile("bar.sync %0, 64;" :: "r"(1 + (wm)) : "memory")
#define OFF_RECV   0
#define OFF_SEND   512
#define OFF_BE     1024
#define OFF_B2V    1536
#define OFF_ACH    2048     /* 2 x 10240 A chunk buffers [128][20] */
#define OFF_A2     22528    /* 128 x 132 floats = 67584 */
#define SMEM_TOTAL 90112

__device__ __forceinline__ void mma_frag_ldgW(float (&acc)[2][8][4],
        const uint32_t* As, int AST, const float* __restrict__ Wchunk,
        int wm, int wn, int lid)
{
    const int g = lid >> 2, tg = lid & 3;
    float4 w[8];
    const float4* wp = (const float4*)Wchunk + wn * 256 + lid;
#pragma unroll
    for (int nt = 0; nt < 8; nt++) w[nt] = __ldg(wp + nt * 32);
    uint32_t a[2][2][4];
#pragma unroll
    for (int f = 0; f < 2; f++) {
        const uint32_t* p = As + (wm * 32 + f * 16 + g) * AST + tg;
#pragma unroll
        for (int ks = 0; ks < 2; ks++) {
            a[f][ks][0] = p[ks * 8];
            a[f][ks][1] = p[8 * AST + ks * 8];
            a[f][ks][2] = p[ks * 8 + 4];
            a[f][ks][3] = p[8 * AST + ks * 8 + 4];
        }
    }
#pragma unroll
    for (int nt = 0; nt < 8; nt++) {
        uint32_t bx = __float_as_uint(w[nt].x), by = __float_as_uint(w[nt].y);
        uint32_t bz = __float_as_uint(w[nt].z), bw = __float_as_uint(w[nt].w);
        mma8(acc[0][nt], a[0][0][0], a[0][0][1], a[0][0][2], a[0][0][3], bx, by);
        mma8(acc[1][nt], a[1][0][0], a[1][0][1], a[1][0][2], a[1][0][3], bx, by);
        mma8(acc[0][nt], a[0][1][0], a[0][1][1], a[0][1][2], a[0][1][3], bz, bw);
        mma8(acc[1][nt], a[1][1][0], a[1][1][1], a[1][1][2], a[1][1][3], bz, bw);
    }
}
__device__ __forceinline__ void mma_frag_smemW(float (&acc)[2][8][4],
        const uint32_t* As, int AST, const float4* Wc, int wm, int wn, int lid)
{
    const int g = lid >> 2, tg = lid & 3;
    uint32_t a[2][2][4];
#pragma unroll
    for (int f = 0; f < 2; f++) {
        const uint32_t* p = As + (wm * 32 + f * 16 + g) * AST + tg;
#pragma unroll
        for (int ks = 0; ks < 2; ks++) {
            a[f][ks][0] = p[ks * 8];
            a[f][ks][1] = p[8 * AST + ks * 8];
            a[f][ks][2] = p[ks * 8 + 4];
            a[f][ks][3] = p[8 * AST + ks * 8 + 4];
        }
    }
    const float4* wp = Wc + wn * 256 + lid;
#pragma unroll
    for (int nt = 0; nt < 8; nt++) {
        float4 bv = wp[nt * 32];
        uint32_t bx = __float_as_uint(bv.x), by = __float_as_uint(bv.y);
        uint32_t bz = __float_as_uint(bv.z), bw = __float_as_uint(bv.w);
        mma8(acc[0][nt], a[0][0][0], a[0][0][1], a[0][0][2], a[0][0][3], bx, by);
        mma8(acc[1][nt], a[1][0][0], a[1][0][1], a[1][0][2], a[1][0][3], bx, by);
        mma8(acc[0][nt], a[0][1][0], a[0][1][1], a[0][1][2], a[0][1][3], bz, bw);
        mma8(acc[1][nt], a[1][1][0], a[1][1][1], a[1][1][2], a[1][1][3], bz, bw);
    }
}
__device__ __forceinline__ void layer2_direct(float (&acc)[2][8][4], char* smem,
        const float* __restrict__ Wfrag, int wm, int wn, int lid)
{
#pragma unroll
    for (int c = 0; c < 8; c++) {
        mma_frag_ldgW(acc, (const uint32_t*)(smem + OFF_A2) + c * 16, 132,
                      Wfrag + c * 2048, wm, wn, lid);
    }
}
template<bool ADDG>
__device__ __forceinline__ void epi1(float (&acc)[2][8][4], char* smem,
                                     int wm, int wn, int lid)
{
    float* A2 = (float*)(smem + OFF_A2);
    const float* be = (const float*)(smem + OFF_BE);
    const int g = lid >> 2, tg = lid & 3;
#pragma unroll
    for (int f = 0; f < 2; f++) {
        int r = wm * 32 + f * 16 + g;
#pragma unroll
        for (int nt = 0; nt < 8; nt++) {
            int n0 = wn * 64 + nt * 8 + tg * 2;
            float be0 = be[n0], be1 = be[n0 + 1];
            float g0x = 0.f, g0y = 0.f, g1x = 0.f, g1y = 0.f;
            if (ADDG) {
                float2 G0 = *(float2*)(A2 + r * 132 + n0);
                float2 G1 = *(float2*)(A2 + (r + 8) * 132 + n0);
                g0x = G0.x; g0y = G0.y; g1x = G1.x; g1y = G1.y;
            }
            float v0 = acc[f][nt][0] + be0 + g0x;
            float v1 = acc[f][nt][1] + be1 + g0y;
            float v2 = acc[f][nt][2] + be0 + g1x;
            float v3 = acc[f][nt][3] + be1 + g1y;
            v0 = (v0 > 0.f) ? v0 : expm1f(v0);
            v1 = (v1 > 0.f) ? v1 : expm1f(v1);
            v2 = (v2 > 0.f) ? v2 : expm1f(v2);
            v3 = (v3 > 0.f) ? v3 : expm1f(v3);
            *(float2*)(A2 + r * 132 + n0)       = make_float2(rtf(v0), rtf(v1));
            *(float2*)(A2 + (r + 8) * 132 + n0) = make_float2(rtf(v2), rtf(v3));
#pragma unroll
            for (int q = 0; q < 4; q++) acc[f][nt][q] = 0.f;
        }
    }
}
template<bool ROUND>
__device__ __forceinline__ void epi2(float (&acc)[2][8][4], char* smem,
                                     int wm, int wn, int lid)
{
    float* A2 = (float*)(smem + OFF_A2);
    const float* be = (const float*)(smem + OFF_B2V);
    const int g = lid >> 2, tg = lid & 3;
#pragma unroll
    for (int f = 0; f < 2; f++) {
        int r = wm * 32 + f * 16 + g;
#pragma unroll
        for (int nt = 0; nt < 8; nt++) {
            int n0 = wn * 64 + nt * 8 + tg * 2;
            float be0 = be[n0], be1 = be[n0 + 1];
            float v0 = acc[f][nt][0] + be0;
            float v1 = acc[f][nt][1] + be1;
            float v2 = acc[f][nt][2] + be0;
            float v3 = acc[f][nt][3] + be1;
            v0 = (v0 > 0.f) ? v0 : expm1f(v0);
            v1 = (v1 > 0.f) ? v1 : expm1f(v1);
            v2 = (v2 > 0.f) ? v2 : expm1f(v2);
            v3 = (v3 > 0.f) ? v3 : expm1f(v3);
            if (ROUND) { v0 = rtf(v0); v1 = rtf(v1); v2 = rtf(v2); v3 = rtf(v3); }
            *(float2*)(A2 + r * 132 + n0)       = make_float2(v0, v1);
            *(float2*)(A2 + (r + 8) * 132 + n0) = make_float2(v2, v3);
        }
    }
}
__device__ __forceinline__ void store_tile(char* smem, float* out, int row0, int tid,
                                           int ostride, int ocol)
{
    const float* A2 = (const float*)(smem + OFF_A2);
#pragma unroll
    for (int i = 0; i < 16; i++) {
        int idx4 = i * 256 + tid;
        int row = idx4 >> 5, c4 = idx4 & 31;
        float4 v = *(const float4*)(A2 + row * 132 + c4 * 4);
        *(float4*)(out + (size_t)(row0 + row) * ostride + ocol + c4 * 4) = v;
    }
}
__device__ __forceinline__ void stats_only(char* smem, int tid, int bx,
                                           float* psum, float* psq)
{
    if (tid >= 128) return;
    const float* A2 = (const float*)(smem + OFF_A2);
    float S = 0.f, Q = 0.f;
#pragma unroll 8
    for (int r = 0; r < 128; r++) {
        float x = A2[r * 132 + tid];
        S += x; Q += x * x;
    }
    psum[(size_t)bx * 128 + tid] = S;
    psq [(size_t)bx * 128 + tid] = Q;
}
#define ACC_DECL float acc[2][8][4]; \
    _Pragma("unroll") for (int f_ = 0; f_ < 2; f_++) \
    _Pragma("unroll") for (int n_ = 0; n_ < 8; n_++) \
    _Pragma("unroll") for (int q_ = 0; q_ < 4; q_++) acc[f_][n_][q_] = 0.f;

// =================== M=64 machinery (R13 config: 32x32 tiles, occ 3) ==========
#define PAIR_BAR128(wm) asm volatile("bar.sync %0, 128;" :: "r"(1 + (wm)) : "memory")
#define E_RECV   0
#define E_SEND   256
#define E_BE     512
#define E_B2V    1024
#define E_ACH    1536      /* 2 x 5120 A chunk buffers [64][20] */
#define E_A2     11776     /* 64 x 132 floats = 33792 */
#define E_SMEM   45568

__device__ __forceinline__ void mma_frag64(float (&acc)[2][4][4],
        const uint32_t* As, int AST, const float* __restrict__ Wchunk,
        int wm, int wn, int lid)
{
    const int g = lid >> 2, tg = lid & 3;
    float4 w[4];
    const float4* wp = (const float4*)Wchunk + wn * 128 + lid;
#pragma unroll
    for (int nt = 0; nt < 4; nt++) w[nt] = __ldg(wp + nt * 32);
    uint32_t a[2][2][4];
#pragma unroll
    for (int f = 0; f < 2; f++) {
        const uint32_t* p = As + (wm * 32 + f * 16 + g) * AST + tg;
#pragma unroll
        for (int ks = 0; ks < 2; ks++) {
            a[f][ks][0] = p[ks * 8];
            a[f][ks][1] = p[8 * AST + ks * 8];
            a[f][ks][2] = p[ks * 8 + 4];
            a[f][ks][3] = p[8 * AST + ks * 8 + 4];
        }
    }
#pragma unroll
    for (int nt = 0; nt < 4; nt++) {
        uint32_t bx = __float_as_uint(w[nt].x), by = __float_as_uint(w[nt].y);
        uint32_t bz = __float_as_uint(w[nt].z), bw = __float_as_uint(w[nt].w);
        mma8(acc[0][nt], a[0][0][0], a[0][0][1], a[0][0][2], a[0][0][3], bx, by);
        mma8(acc[1][nt], a[1][0][0], a[1][0][1], a[1][0][2], a[1][0][3], bx, by);
        mma8(acc[0][nt], a[0][1][0], a[0][1][1], a[0][1][2], a[0][1][3], bz, bw);
        mma8(acc[1][nt], a[1][1][0], a[1][1][1], a[1][1][2], a[1][1][3], bz, bw);
    }
}
// pair = 4 warps sharing wm (wid&1): 128 threads, pt = wn*32+lid
__device__ __forceinline__ void issue_a64(int c, int buf, uint32_t sb, int pt, int wm,
                                          const float* Asrc, int row0) {
    int row = wm * 32 + (pt >> 2), c4 = pt & 3;
    cp16(sb + E_ACH + buf * 5120 + row * 80 + c4 * 16,
         Asrc + (size_t)(row0 + row) * 128 + c * 16 + c4 * 4);
    asm volatile("cp.async.commit_group;");
}
__device__ __forceinline__ void layer1_64(float (&acc)[2][4][4], char* smem, uint32_t sb,
        const float* Asrc, int row0, const float* __restrict__ Wfrag,
        int wm, int wn, int lid, int pt, bool preissued)
{
    if (!preissued) {
        issue_a64(0, 0, sb, pt, wm, Asrc, row0);
        issue_a64(1, 1, sb, pt, wm, Asrc, row0);
    }
    for (int c = 0; c < 8; c++) {
        int buf = c & 1;
        if (c < 7) asm volatile("cp.async.wait_group 1;");
        else       asm volatile("cp.async.wait_group 0;");
        PAIR_BAR128(wm);
        mma_frag64(acc, (const uint32_t*)(smem + E_ACH + buf * 5120), 20,
                   Wfrag + c * 2048, wm, wn, lid);
        PAIR_BAR128(wm);
        if (c + 2 < 8) issue_a64(c + 2, buf, sb, pt, wm, Asrc, row0);
    }
}
__device__ __forceinline__ void layer2_64(float (&acc)[2][4][4], char* smem,
        const float* __restrict__ Wfrag, int wm, int wn, int lid)
{
#pragma unroll
    for (int c = 0; c < 8; c++) {
        mma_frag64(acc, (const uint32_t*)(smem + E_A2) + c * 16, 132,
                   Wfrag + c * 2048, wm, wn, lid);
    }
}
template<bool ADDG>
__device__ __forceinline__ void epi1_64(float (&acc)[2][4][4], char* smem,
                                        int wm, int wn, int lid)
{
    float* A2 = (float*)(smem + E_A2);
    const float* be = (const float*)(smem + E_BE);
    const int g = lid >> 2, tg = lid & 3;
#pragma unroll
    for (int f = 0; f < 2; f++) {
        int r = wm * 32 + f * 16 + g;
#pragma unroll
        for (int nt = 0; nt < 4; nt++) {
            int n0 = wn * 32 + nt * 8 + tg * 2;
            float be0 = be[n0], be1 = be[n0 + 1];
            float g0x = 0.f, g0y = 0.f, g1x = 0.f, g1y = 0.f;
            if (ADDG) {
                float2 G0 = *(float2*)(A2 + r * 132 + n0);
                float2 G1 = *(float2*)(A2 + (r + 8) * 132 + n0);
                g0x = G0.x; g0y = G0.y; g1x = G1.x; g1y = G1.y;
            }
            float v0 = acc[f][nt][0] + be0 + g0x;
            float v1 = acc[f][nt][1] + be1 + g0y;
            float v2 = acc[f][nt][2] + be0 + g1x;
            float v3 = acc[f][nt][3] + be1 + g1y;
            v0 = (v0 > 0.f) ? v0 : expm1f(v0);
            v1 = (v1 > 0.f) ? v1 : expm1f(v1);
            v2 = (v2 > 0.f) ? v2 : expm1f(v2);
            v3 = (v3 > 0.f) ? v3 : expm1f(v3);
            *(float2*)(A2 + r * 132 + n0)       = make_float2(rtf(v0), rtf(v1));
            *(float2*)(A2 + (r + 8) * 132 + n0) = make_float2(rtf(v2), rtf(v3));
#pragma unroll
            for (int q = 0; q < 4; q++) acc[f][nt][q] = 0.f;
        }
    }
}
template<bool ROUND>
__device__ __forceinline__ void epi2_64(float (&acc)[2][4][4], char* smem,
                                        int wm, int wn, int lid)
{
    float* A2 = (float*)(smem + E_A2);
    const float* be = (const float*)(smem + E_B2V);
    const int g = lid >> 2, tg = lid & 3;
#pragma unroll
    for (int f = 0; f < 2; f++) {
        int r = wm * 32 + f * 16 + g;
#pragma unroll
        for (int nt = 0; nt < 4; nt++) {
            int n0 = wn * 32 + nt * 8 + tg * 2;
            float be0 = be[n0], be1 = be[n0 + 1];
            float v0 = acc[f][nt][0] + be0;
            float v1 = acc[f][nt][1] + be1;
            float v2 = acc[f][nt][2] + be0;
            float v3 = acc[f][nt][3] + be1;
            v0 = (v0 > 0.f) ? v0 : expm1f(v0);
            v1 = (v1 > 0.f) ? v1 : expm1f(v1);
            v2 = (v2 > 0.f) ? v2 : expm1f(v2);
            v3 = (v3 > 0.f) ? v3 : expm1f(v3);
            if (ROUND) { v0 = rtf(v0); v1 = rtf(v1); v2 = rtf(v2); v3 = rtf(v3); }
            *(float2*)(A2 + r * 132 + n0)       = make_float2(v0, v1);
            *(float2*)(A2 + (r + 8) * 132 + n0) = make_float2(v2, v3);
        }
    }
}
__device__ __forceinline__ void store_tile64(char* smem, float* out, int row0, int tid,
                                             int ostride, int ocol)
{
    const float* A2 = (const float*)(smem + E_A2);
#pragma unroll
    for (int i = 0; i < 8; i++) {
        int idx4 = i * 256 + tid;
        int row = idx4 >> 5, c4 = idx4 & 31;
        float4 v = *(const float4*)(A2 + row * 132 + c4 * 4);
        *(float4*)(out + (size_t)(row0 + row) * ostride + ocol + c4 * 4) = v;
    }
}
// edge stats + node partials (channel-major psum)
__device__ __forceinline__ void stats64(char* smem, int row0, int tid, int bx,
        float* psum, float* psq, float* pnode)
{
    if (tid >= 128) return;
    const float* A2 = (const float*)(smem + E_A2);
    float S = 0.f, Q = 0.f, nacc = 0.f;
    int slot = 0;
    int nxt = 23 - (row0 % 23);
    float* pb = pnode + (size_t)bx * 4 * 128;
#pragma unroll 4
    for (int r = 0; r < 64; r++) {
        if (r == nxt) { pb[slot * 128 + tid] = nacc; slot++; nacc = 0.f; nxt += 23; }
        float x = A2[r * 132 + tid];
        S += x; Q += x * x; nacc += x;
    }
    pb[slot * 128 + tid] = nacc;
    psum[(size_t)tid * GE64 + bx] = S;
    psq [(size_t)tid * GE64 + bx] = Q;
}
// node stats (block-major psum), 64-row A2
__device__ __forceinline__ void stats_only64(char* smem, int tid, int bx,
                                             float* psum, float* psq)
{
    if (tid >= 128) return;
    const float* A2 = (const float*)(smem + E_A2);
    float S = 0.f, Q = 0.f;
#pragma unroll 8
    for (int r = 0; r < 64; r++) {
        float x = A2[r * 132 + tid];
        S += x; Q += x * x;
    }
    psum[(size_t)bx * 128 + tid] = S;
    psq [(size_t)bx * 128 + tid] = Q;
}
__device__ __forceinline__ void fill_edges64(char* smem, int row0, int tid) {
    if (tid < 64) {
        int row = row0 + tid;
        int b = row / NEDGE;
        int e = row - b * NEDGE;
        int r = e / 23;
        int j = e - r * 23;
        int s = j + (j >= r);
        ((int*)(smem + E_RECV))[tid] = b * NKPS + r;
        ((int*)(smem + E_SEND))[tid] = b * NKPS + s;
    }
}
#define ACC64_DECL float acc[2][4][4]; \
    _Pragma("unroll") for (int f_ = 0; f_ < 2; f_++) \
    _Pragma("unroll") for (int n_ = 0; n_ < 4; n_++) \
    _Pragma("unroll") for (int q_ = 0; q_ < 4; q_++) acc[f_][n_][q_] = 0.f;

// =================== kernels ==================================================
__global__ __launch_bounds__(256, 2)
void stage1_mlp(const float* __restrict__ X, const float* __restrict__ W1,
                const float* __restrict__ b1, const float* __restrict__ W2frag,
                const float* __restrict__ b2, float* __restrict__ out,
                float* __restrict__ psum, float* __restrict__ psq)
{
    extern __shared__ char smem[];
    const int tid = threadIdx.x, wid = tid >> 5, lid = tid & 31;
    const int wm = wid & 3, wn = wid >> 2;
    const int row0 = blockIdx.x * 128;
    float* smf = (float*)smem;
    if (tid < 128) { smf[OFF_BE/4 + tid] = b1[tid]; smf[OFF_B2V/4 + tid] = b2[tid]; }
#pragma unroll
    for (int i = 0; i < 8; i++) {
        int idx = i * 256 + tid;
        int row = idx >> 4, col = idx & 15;
        float av = (col < 6) ? X[(size_t)(row0 + row) * 6 + col] : 0.f;
        smf[OFF_ACH/4 + row * 20 + col] = rtf(av);
    }
#pragma unroll
    for (int i = 0; i < 8; i++) {
        int o = i * 256 + tid;
        int f4 = o >> 2, reg = o & 3;
        int nb = f4 >> 5, lane = f4 & 31, gg = lane >> 2, tg = lane & 3;
        int n = nb * 8 + gg;
        int k = (reg >> 1) * 8 + (reg & 1) * 4 + tg;
        smf[(OFF_ACH + 10240)/4 + o] = rtf((k < 6) ? W1[n * 6 + k] : 0.f);
    }
    __syncthreads();
    ACC_DECL
    mma_frag_smemW(acc, (const uint32_t*)(smem + OFF_ACH), 20,
                   (const float4*)(smem + OFF_ACH + 10240), wm, wn, lid);
    epi1<false>(acc, smem, wm, wn, lid);
    __syncthreads();
    layer2_direct(acc, smem, W2frag, wm, wn, lid);
    epi2<true>(acc, smem, wm, wn, lid);
    __syncthreads();
    store_tile(smem, out, row0, tid, 128, 0);
    stats_only(smem, tid, blockIdx.x, psum, psq);
}

// stage-3 node MLP on the M=64 path (grid 384, occ 3)
__global__ __launch_bounds__(256, 3)
void node64_mlp(const float* __restrict__ A, const float* __restrict__ W1frag,
                const float* __restrict__ b1, const float* __restrict__ W2frag,
                const float* __restrict__ b2, float* __restrict__ out,
                float* __restrict__ psum, float* __restrict__ psq)
{
    extern __shared__ char smem[];
    const uint32_t sb = smem_u32(smem);
    const int tid = threadIdx.x, wid = tid >> 5, lid = tid & 31;
    const int wm = wid & 1, wn = wid >> 1;
    const int pt = wn * 32 + lid;
    const int row0 = blockIdx.x * 64;
    float* smf = (float*)smem;
    if (tid < 128) { smf[E_BE/4 + tid] = b1[tid]; smf[E_B2V/4 + tid] = b2[tid]; }
    __syncthreads();
    ACC64_DECL
    layer1_64(acc, smem, sb, A, row0, W1frag, wm, wn, lid, pt, false);
    epi1_64<false>(acc, smem, wm, wn, lid);
    __syncthreads();
    layer2_64(acc, smem, W2frag, wm, wn, lid);
    epi2_64<true>(acc, smem, wm, wn, lid);
    __syncthreads();
    store_tile64(smem, out, row0, tid, 128, 0);
    stats_only64(smem, tid, blockIdx.x, psum, psq);
}

// PS[:, blk*128 : +128] = A @ Wfrag(blk)^T, raw fp32  (M=64 tiles, occ 3)
__global__ __launch_bounds__(256, 3)
void gemm_node(const float* __restrict__ A, const float* __restrict__ Wfrag,
               float* __restrict__ PS)
{
    extern __shared__ char smem[];
    const uint32_t sb = smem_u32(smem);
    const int tid = threadIdx.x, wid = tid >> 5, lid = tid & 31;
    const int wm = wid & 1, wn = wid >> 1;
    const int pt = wn * 32 + lid;
    const int row0 = blockIdx.x * 64;
    const int blk = blockIdx.y;
    ACC64_DECL
    layer1_64(acc, smem, sb, A, row0, Wfrag + (size_t)blk * 16384, wm, wn, lid, pt, false);
    float* A2 = (float*)(smem + E_A2);
    const int g = lid >> 2, tg = lid & 3;
#pragma unroll
    for (int f = 0; f < 2; f++) {
        int r = wm * 32 + f * 16 + g;
#pragma unroll
        for (int nt = 0; nt < 4; nt++) {
            int n0 = wn * 32 + nt * 8 + tg * 2;
            *(float2*)(A2 + r * 132 + n0)       = make_float2(acc[f][nt][0], acc[f][nt][1]);
            *(float2*)(A2 + (r + 8) * 132 + n0) = make_float2(acc[f][nt][2], acc[f][nt][3]);
        }
    }
    __syncthreads();
    store_tile64(smem, PS, row0, tid, 256, blk * 128);
}

// stage 2 edges (M=64, occ 3)
__global__ __launch_bounds__(256, 3)
void edge_stage2(const float* __restrict__ PS, const float* __restrict__ beff,
                 const float* __restrict__ W2frag, const float* __restrict__ b2,
                 float* __restrict__ out, float* __restrict__ psum, float* __restrict__ psq,
                 float* __restrict__ pnode)
{
    extern __shared__ char smem[];
    const int tid = threadIdx.x, wid = tid >> 5, lid = tid & 31;
    const int wm = wid & 1, wn = wid >> 1;
    const int row0 = blockIdx.x * 64;
    float* smf = (float*)smem;
    fill_edges64(smem, row0, tid);
    if (tid < 128) { smf[E_BE/4 + tid] = beff[tid]; smf[E_B2V/4 + tid] = b2[tid]; }
    __syncthreads();
    const int* rs = (const int*)(smem + E_RECV);
    const int* ss = (const int*)(smem + E_SEND);
    float* A2 = (float*)(smem + E_A2);
    const float* be = smf + E_BE/4;
#pragma unroll
    for (int i = 0; i < 8; i++) {
        int idx4 = i * 256 + tid;
        int row = idx4 >> 5, c4 = idx4 & 31;
        float4 p = *(const float4*)(PS + (size_t)rs[row] * 256 + c4 * 4);
        float4 s = *(const float4*)(PS + (size_t)ss[row] * 256 + 128 + c4 * 4);
        float v0 = p.x + s.x + be[c4 * 4];
        float v1 = p.y + s.y + be[c4 * 4 + 1];
        float v2 = p.z + s.z + be[c4 * 4 + 2];
        float v3 = p.w + s.w + be[c4 * 4 + 3];
        v0 = (v0 > 0.f) ? v0 : expm1f(v0);
        v1 = (v1 > 0.f) ? v1 : expm1f(v1);
        v2 = (v2 > 0.f) ? v2 : expm1f(v2);
        v3 = (v3 > 0.f) ? v3 : expm1f(v3);
        *(float4*)(A2 + row * 132 + c4 * 4) = make_float4(rtf(v0), rtf(v1), rtf(v2), rtf(v3));
    }
    __syncthreads();
    ACC64_DECL
    layer2_64(acc, smem, W2frag, wm, wn, lid);
    epi2_64<true>(acc, smem, wm, wn, lid);
    __syncthreads();
    store_tile64(smem, out, row0, tid, 128, 0);
    stats64(smem, row0, tid, blockIdx.x, psum, psq, pnode);
}

// stage 4 edges (M=64, occ 3)
__global__ __launch_bounds__(256, 3)
void edge_stage4(const float* __restrict__ PS3, const float* __restrict__ H2,
                 const float* __restrict__ SKIPfrag, const float* __restrict__ beff,
                 const float* __restrict__ W2frag, const float* __restrict__ b2,
                 float* __restrict__ psum, float* __restrict__ psq,
                 float* __restrict__ pnode)
{
    extern __shared__ char smem[];
    const uint32_t sb = smem_u32(smem);
    const int tid = threadIdx.x, wid = tid >> 5, lid = tid & 31;
    const int wm = wid & 1, wn = wid >> 1;
    const int pt = wn * 32 + lid;
    const int row0 = blockIdx.x * 64;
    float* smf = (float*)smem;
    fill_edges64(smem, row0, tid);
    if (tid < 128) { smf[E_BE/4 + tid] = beff[tid]; smf[E_B2V/4 + tid] = b2[tid]; }
    issue_a64(0, 0, sb, pt, wm, H2, row0);
    issue_a64(1, 1, sb, pt, wm, H2, row0);
    __syncthreads();
    const int* rs = (const int*)(smem + E_RECV);
    const int* ss = (const int*)(smem + E_SEND);
    float* A2 = (float*)(smem + E_A2);
#pragma unroll
    for (int i = 0; i < 8; i++) {
        int idx4 = i * 256 + tid;
        int row = idx4 >> 5, c4 = idx4 & 31;
        float4 p = *(const float4*)(PS3 + (size_t)rs[row] * 256 + c4 * 4);
        float4 s = *(const float4*)(PS3 + (size_t)ss[row] * 256 + 128 + c4 * 4);
        *(float4*)(A2 + row * 132 + c4 * 4) =
            make_float4(p.x + s.x, p.y + s.y, p.z + s.z, p.w + s.w);
    }
    ACC64_DECL
    layer1_64(acc, smem, sb, H2, row0, SKIPfrag, wm, wn, lid, pt, true);
    epi1_64<true>(acc, smem, wm, wn, lid);
    __syncthreads();
    layer2_64(acc, smem, W2frag, wm, wn, lid);
    epi2_64<false>(acc, smem, wm, wn, lid);
    __syncthreads();
    stats64(smem, row0, tid, blockIdx.x, psum, psq, pnode);
}

// combine node partials (stage-2 path): 64-row blocks
__global__ void node_combine(const float* __restrict__ pnode,
                             const float* __restrict__ s, const float* __restrict__ t,
                             float* __restrict__ outn)
{
    int idx = blockIdx.x * 256 + threadIdx.x;
    int n = idx >> 7, c = idx & 127;
    int e0 = n * 23, e1 = e0 + 22;
    int b0 = e0 >> 6, b1 = e1 >> 6;
    int s0 = n - (b0 * 64) / 23;
    float sum = pnode[((size_t)b0 * 4 + s0) * 128 + c];
    if (b1 != b0) {
        int s1 = n - (b1 * 64) / 23;
        sum += pnode[((size_t)b1 * 4 + s1) * 128 + c];
    }
    outn[(size_t)n * 128 + c] = rtf((s[c] * sum + 23.f * t[c]) * (1.f / 24.f));
}

// ---- preps --------------------------------------------------------------------
__device__ __forceinline__ void frag_block(const float* W, int Kin, int kofs,
                                           const float* sv, float* dst, int o)
{
    int c = o >> 11, rem = o & 2047;
    int f4 = rem >> 2, reg = rem & 3;
    int nb = f4 >> 5, lane = f4 & 31;
    int g = lane >> 2, tg = lane & 3;
    int n = nb * 8 + g;
    int k = c * 16 + (reg >> 1) * 8 + (reg & 1) * 4 + tg;
    float v = W[(size_t)n * Kin + kofs + k];
    if (sv) v *= sv[k];
    dst[o] = __uint_as_float(f2tf(v));
}
__device__ __forceinline__ void bias_block(const float* W, int Kin, const float* b,
                                           const float* ta, const float* tb,
                                           float* beff, int n, int tid)
{
    float partial = 0.f;
    for (int k = tid; k < Kin; k += 256) {
        float t = (k < 256) ? ta[k & 127] : tb[k - 256];
        partial += W[(size_t)n * Kin + k] * t;
    }
    __shared__ float red[256];
    red[tid] = partial;
    __syncthreads();
    for (int off = 128; off; off >>= 1) {
        if (tid < off) red[tid] += red[tid + off];
        __syncthreads();
    }
    if (tid == 0) beff[n] = b[n] + red[0];
}
__device__ __forceinline__ void bn_inline(const float* psum, const float* psq, int nblk,
                                          float Minv, const float* g, const float* be,
                                          float* ss, float* st, int tid)
{
    if (tid < 128) {
        float S = 0.f, Q = 0.f;
        for (int i = 0; i < nblk; i++) {
            S += psum[i * 128 + tid];
            Q += psq [i * 128 + tid];
        }
        float mean = S * Minv;
        float var  = Q * Minv - mean * mean;
        float inv  = rsqrtf(var + BN_EPS);
        float sv   = g[tid] * inv;
        ss[tid] = sv;
        st[tid] = be[tid] - mean * sv;
    }
    __syncthreads();
}

__global__ void prep_indep(const float* W0, const float* W1, const float* W2,
                           const float* W3, const float* W4,
                           float* D0, float* D1, float* D2, float* D3, float* D4)
{
    int sel = blockIdx.x >> 6;
    int o = (blockIdx.x & 63) * 256 + threadIdx.x;
    const float* W = (sel == 0) ? W0 : (sel == 1) ? W1 : (sel == 2) ? W2
                   : (sel == 3) ? W3 : W4;
    float* D = (sel == 0) ? D0 : (sel == 1) ? D1 : (sel == 2) ? D2
             : (sel == 3) ? D3 : D4;
    frag_block(W, 128, 0, nullptr, D, o);
}
__global__ void prep_stage2(const float* __restrict__ W1, const float* __restrict__ b1,
                            const float* __restrict__ psum, const float* __restrict__ psq,
                            float Minv, const float* __restrict__ gg,
                            const float* __restrict__ gb,
                            float* __restrict__ psfrag, float* __restrict__ beff)
{
    __shared__ float ss[128], st[128];
    int bx = blockIdx.x, tid = threadIdx.x;
    bn_inline(psum, psq, GN_BLK, Minv, gg, gb, ss, st, tid);
    if (bx < 64)        frag_block(W1, 256, 0,   ss, psfrag,          bx * 256 + tid);
    else if (bx < 128)  frag_block(W1, 256, 128, ss, psfrag + 16384,  (bx - 64) * 256 + tid);
    else                bias_block(W1, 256, b1, st, nullptr, beff, bx - 128, tid);
}
__global__ void prep_stage4(const float* __restrict__ W1, const float* __restrict__ b1,
                            const float* __restrict__ psum, const float* __restrict__ psq,
                            float Minv, const float* __restrict__ gg,
                            const float* __restrict__ gb,
                            const float* __restrict__ s2, const float* __restrict__ t2,
                            float* __restrict__ psfrag, float* __restrict__ skipfrag,
                            float* __restrict__ beff)
{
    __shared__ float ss[128], st[128];
    int bx = blockIdx.x, tid = threadIdx.x;
    bn_inline(psum, psq, GN64, Minv, gg, gb, ss, st, tid);
    if (bx < 64)        frag_block(W1, 384, 0,   ss, psfrag,          bx * 256 + tid);
    else if (bx < 128)  frag_block(W1, 384, 128, ss, psfrag + 16384,  (bx - 64) * 256 + tid);
    else if (bx < 192)  frag_block(W1, 384, 256, s2, skipfrag,        (bx - 128) * 256 + tid);
    else                bias_block(W1, 384, b1, st, t2, beff, bx - 192, tid);
}

__global__ void bn_edge(const float* __restrict__ psum, const float* __restrict__ psq,
                        float Minv, const float* __restrict__ g, const float* __restrict__ be,
                        float* __restrict__ s, float* __restrict__ t)
{
    const int c = blockIdx.x, tid = threadIdx.x;
    float S = 0.f, Q = 0.f;
    for (int i = tid; i < GE64; i += 256) {
        S += psum[(size_t)c * GE64 + i];
        Q += psq [(size_t)c * GE64 + i];
    }
    __shared__ float rs[256], rq[256];
    rs[tid] = S; rq[tid] = Q;
    __syncthreads();
    for (int off = 128; off; off >>= 1) {
        if (tid < off) { rs[tid] += rs[tid + off]; rq[tid] += rq[tid + off]; }
        __syncthreads();
    }
    if (tid == 0) {
        float mean = rs[0] * Minv;
        float var  = rq[0] * Minv - mean * mean;
        float inv  = rsqrtf(var + BN_EPS);
        float sv   = g[c] * inv;
        s[c] = sv;
        t[c] = be[c] - mean * sv;
    }
}

__global__ void final_proj(const float* __restrict__ pnode,
                           const float* __restrict__ s, const float* __restrict__ t,
                           const float* __restrict__ fo_w, const float* __restrict__ fo_b,
                           float* __restrict__ out)
{
    int b = blockIdx.x;
    int c = threadIdx.x;
    float sc = s[c], tc = t[c];
    float a0 = 0.f, a1 = 0.f;
#pragma unroll
    for (int n = 0; n < NKPS; n++) {
        int nn = b * NKPS + n;
        int e0 = nn * 23, e1 = e0 + 22;
        int b0 = e0 >> 6, b1e = e1 >> 6;
        int s0 = nn - (b0 * 64) / 23;
        float sum = pnode[((size_t)b0 * 4 + s0) * 128 + c];
        if (b1e != b0) {
            int s1 = nn - (b1e * 64) / 23;
            sum += pnode[((size_t)b1e * 4 + s1) * 128 + c];
        }
        float v = (sc * sum + 23.f * tc) * (1.f / 24.f);
        a0 = fmaf(v, fo_w[n * 128 + c],        a0);
        a1 = fmaf(v, fo_w[3072 + n * 128 + c], a1);
    }
    __shared__ float r0[128], r1[128];
    r0[c] = a0; r1[c] = a1;
    __syncthreads();
    for (int off = 64; off; off >>= 1) {
        if (c < off) { r0[c] += r0[c + off]; r1[c] += r1[c + off]; }
        __syncthreads();
    }
    if (c == 0) {
        out[b * 2 + 0] = r0[0] + fo_b[0];
        out[b * 2 + 1] = r1[0] + fo_b[1];
    }
}

// ---- launch -------------------------------------------------------------------
extern "C" void kernel_launch(void* const* d_in, const int* in_sizes, int n_in,
                              void* d_out, int out_size)
{
    const float** I = (const float**)d_in;
    const float* inputs = I[0];
    const float *fo_w = I[3], *fo_b = I[4];
    const float *m1w1 = I[5],  *m1b1 = I[6],  *m1w2 = I[7],  *m1b2 = I[8],  *m1g = I[9],  *m1be = I[10];
    const float *m2w1 = I[11], *m2b1 = I[12], *m2w2 = I[13], *m2b2 = I[14], *m2g = I[15], *m2be = I[16];
    const float *m3w1 = I[17], *m3b1 = I[18], *m3w2 = I[19], *m3b2 = I[20], *m3g = I[21], *m3be = I[22];
    const float *m4w1 = I[23], *m4b1 = I[24], *m4w2 = I[25], *m4b2 = I[26], *m4g = I[27], *m4be = I[28];
    float* out = (float*)d_out;

    float *bufA, *n1, *n2, *n3, *ps, *pnode, *psfrag, *skipfrag, *w1f3;
    float *l2m1, *l2m2, *l2m3, *l2m4;
    float *beff, *psum, *psq, *sA, *tA;
    cudaGetSymbolAddress((void**)&bufA, g_bufA);
    cudaGetSymbolAddress((void**)&n1, g_n1);
    cudaGetSymbolAddress((void**)&n2, g_n2);
    cudaGetSymbolAddress((void**)&n3, g_n3);
    cudaGetSymbolAddress((void**)&ps, g_ps);
    cudaGetSymbolAddress((void**)&pnode, g_pnode);
    cudaGetSymbolAddress((void**)&psfrag, g_psfrag);
    cudaGetSymbolAddress((void**)&skipfrag, g_skipfrag);
    cudaGetSymbolAddress((void**)&w1f3, g_w1f3);
    cudaGetSymbolAddress((void**)&l2m1, g_l2m1);
    cudaGetSymbolAddress((void**)&l2m2, g_l2m2);
    cudaGetSymbolAddress((void**)&l2m3, g_l2m3);
    cudaGetSymbolAddress((void**)&l2m4, g_l2m4);
    cudaGetSymbolAddress((void**)&beff, g_beff);
    cudaGetSymbolAddress((void**)&psum, g_psum);
    cudaGetSymbolAddress((void**)&psq, g_psq);
    cudaGetSymbolAddress((void**)&sA, g_s);
    cudaGetSymbolAddress((void**)&tA, g_t);

    cudaFuncSetAttribute(stage1_mlp,  cudaFuncAttributeMaxDynamicSharedMemorySize, SMEM_TOTAL);
    cudaFuncSetAttribute(node64_mlp,  cudaFuncAttributeMaxDynamicSharedMemorySize, E_SMEM);
    cudaFuncSetAttribute(gemm_node,   cudaFuncAttributeMaxDynamicSharedMemorySize, E_SMEM);
    cudaFuncSetAttribute(edge_stage2, cudaFuncAttributeMaxDynamicSharedMemorySize, E_SMEM);
    cudaFuncSetAttribute(edge_stage4, cudaFuncAttributeMaxDynamicSharedMemorySize, E_SMEM);

    const float MinvN = 1.0f / (float)M_NODE;
    const float MinvE = 1.0f / (float)M_EDGE;
    dim3 gnode(GN64, 2);

    // #1: all scale-independent weight frags
    prep_indep<<<320, 256>>>(m1w2, m2w2, m3w1, m3w2, m4w2,
                             l2m1, l2m2, w1f3, l2m3, l2m4);
    // #2: stage 1 (M=128)
    stage1_mlp<<<GN_BLK, 256, SMEM_TOTAL>>>(inputs, m1w1, m1b1, l2m1, m1b2, n1, psum, psq);
    // #3: stage-2 prep (BN1 fused, 192 stat blocks)
    prep_stage2<<<256, 256>>>(m2w1, m2b1, psum, psq, MinvN, m1g, m1be, psfrag, beff);
    // #4: node P/S GEMM (M=64, occ 3)  <-- profiled launch
    gemm_node<<<gnode, 256, E_SMEM>>>(n1, psfrag, ps);
    // #5: edges stage 2 (M=64, occ 3)
    edge_stage2<<<GE64, 256, E_SMEM>>>(ps, beff, l2m2, m2b2, bufA, psum, psq, pnode);
    // #6: BN2
    bn_edge<<<128, 256>>>(psum, psq, MinvE, m2g, m2be, sA + 128, tA + 128);
    // #7: edge2node
    node_combine<<<M_NODE * 128 / 256, 256>>>(pnode, sA + 128, tA + 128, n2);
    // #8: stage 3 (M=64, grid 384, occ 3)
    node64_mlp<<<GN64, 256, E_SMEM>>>(n2, w1f3, m3b1, l2m3, m3b2, n3, psum, psq);
    // #9: stage-4 prep (BN3 fused, 384 stat blocks)
    prep_stage4<<<320, 256>>>(m4w1, m4b1, psum, psq, MinvN, m3g, m3be,
                              sA + 128, tA + 128, psfrag, skipfrag, beff);
    // #10: node P/S GEMM for stage 4
    gemm_node<<<gnode, 256, E_SMEM>>>(n3, psfrag, ps);
    // #11: edges stage 4 (M=64, occ 3)
    edge_stage4<<<GE64, 256, E_SMEM>>>(ps, bufA, skipfrag, beff, l2m4, m4b2, psum, psq, pnode);
    // #12: BN4
    bn_edge<<<128, 256>>>(psum, psq, MinvE, m4g, m4be, sA + 384, tA + 384);
    // #13: final projection with fused combine
    final_proj<<<BATCH, 128>>>(pnode, sA + 384, tA + 384, fo_w, fo_b, out);
}

// round 17
// speedup vs baseline: 1.0436x; 1.0048x over previous
#include <cuda_runtime.h>
#include <math.h>
#include <stdint.h>

#define BATCH   1024
#define NKPS    24
#define NEDGE   552
#define M_NODE  (BATCH*NKPS)    // 24576
#define M_EDGE  (BATCH*NEDGE)   // 565248
#define GE64    (M_EDGE/64)     // 8832
#define GN64    (M_NODE/64)     // 384
#define GN_BLK  (M_NODE/128)    // 192
#define BN_EPS  1e-5f

// ---------------- scratch (device globals) ---------------------------------
__device__ float g_bufA[(size_t)M_EDGE*128];   // h2 (x_skip), tf32-rounded
__device__ float g_n1 [(size_t)M_NODE*128];
__device__ float g_n3 [(size_t)M_NODE*128];
__device__ float g_ps [(size_t)M_NODE*256];    // P|S per node, fp32
__device__ float g_pnode[(size_t)GE64*4*128];
__device__ float g_psfrag[2*16384];
__device__ float g_skipfrag[16384];
__device__ float g_w1f3[16384];
__device__ float g_l2m1[16384];
__device__ float g_l2m2[16384];
__device__ float g_l2m3[16384];
__device__ float g_l2m4[16384];
__device__ float g_beff[128];
__device__ float g_psum[(size_t)GE64*128];     // edge: channel-major [128][GE64]; node: block-major
__device__ float g_psq [(size_t)GE64*128];
__device__ float g_s[4*128];
__device__ float g_t[4*128];

// ---------------- helpers ----------------------------------------------------
__device__ __forceinline__ uint32_t smem_u32(const void* p) {
    uint32_t a;
    asm("{ .reg .u64 t; cvta.to.shared.u64 t, %1; cvt.u32.u64 %0, t; }" : "=r"(a) : "l"(p));
    return a;
}
__device__ __forceinline__ void cp16(uint32_t dst, const void* src) {
    asm volatile("cp.async.cg.shared.global [%0], [%1], 16;" :: "r"(dst), "l"(src));
}
__device__ __forceinline__ uint32_t f2tf(float x) {
    uint32_t u;
    asm("cvt.rna.tf32.f32 %0, %1;" : "=r"(u) : "f"(x));
    return u;
}
__device__ __forceinline__ float rtf(float x) { return __uint_as_float(f2tf(x)); }
__device__ __forceinline__ void mma8(float d[4],
                                     uint32_t a0, uint32_t a1, uint32_t a2, uint32_t a3,
                                     uint32_t b0, uint32_t b1) {
    asm volatile("mma.sync.aligned.m16n8k8.row.col.f32.tf32.tf32.f32 "
        "{%0,%1,%2,%3}, {%4,%5,%6,%7}, {%8,%9}, {%0,%1,%2,%3};"
        : "+f"(d[0]), "+f"(d[1]), "+f"(d[2]), "+f"(d[3])
        : "r"(a0), "r"(a1), "r"(a2), "r"(a3), "r"(b0), "r"(b1));
}

// =================== M=128 machinery (stage-1 kernel, occ 2) ==================
#define OFF_BE     1024
#define OFF_B2V    1536
#define OFF_ACH    2048     /* stage-1 A [128][20] + W1 frags */
#define OFF_A2     22528    /* 128 x 132 floats = 67584 */
#define SMEM_TOTAL 90112

__device__ __forceinline__ void mma_frag_ldgW(float (&acc)[2][8][4],
        const uint32_t* As, int AST, const float* __restrict__ Wchunk,
        int wm, int wn, int lid)
{
    const int g = lid >> 2, tg = lid & 3;
    float4 w[8];
    const float4* wp = (const float4*)Wchunk + wn * 256 + lid;
#pragma unroll
    for (int nt = 0; nt < 8; nt++) w[nt] = __ldg(wp + nt * 32);
    uint32_t a[2][2][4];
#pragma unroll
    for (int f = 0; f < 2; f++) {
        const uint32_t* p = As + (wm * 32 + f * 16 + g) * AST + tg;
#pragma unroll
        for (int ks = 0; ks < 2; ks++) {
            a[f][ks][0] = p[ks * 8];
            a[f][ks][1] = p[8 * AST + ks * 8];
            a[f][ks][2] = p[ks * 8 + 4];
            a[f][ks][3] = p[8 * AST + ks * 8 + 4];
        }
    }
#pragma unroll
    for (int nt = 0; nt < 8; nt++) {
        uint32_t bx = __float_as_uint(w[nt].x), by = __float_as_uint(w[nt].y);
        uint32_t bz = __float_as_uint(w[nt].z), bw = __float_as_uint(w[nt].w);
        mma8(acc[0][nt], a[0][0][0], a[0][0][1], a[0][0][2], a[0][0][3], bx, by);
        mma8(acc[1][nt], a[1][0][0], a[1][0][1], a[1][0][2], a[1][0][3], bx, by);
        mma8(acc[0][nt], a[0][1][0], a[0][1][1], a[0][1][2], a[0][1][3], bz, bw);
        mma8(acc[1][nt], a[1][1][0], a[1][1][1], a[1][1][2], a[1][1][3], bz, bw);
    }
}
__device__ __forceinline__ void mma_frag_smemW(float (&acc)[2][8][4],
        const uint32_t* As, int AST, const float4* Wc, int wm, int wn, int lid)
{
    const int g = lid >> 2, tg = lid & 3;
    uint32_t a[2][2][4];
#pragma unroll
    for (int f = 0; f < 2; f++) {
        const uint32_t* p = As + (wm * 32 + f * 16 + g) * AST + tg;
#pragma unroll
        for (int ks = 0; ks < 2; ks++) {
            a[f][ks][0] = p[ks * 8];
            a[f][ks][1] = p[8 * AST + ks * 8];
            a[f][ks][2] = p[ks * 8 + 4];
            a[f][ks][3] = p[8 * AST + ks * 8 + 4];
        }
    }
    const float4* wp = Wc + wn * 256 + lid;
#pragma unroll
    for (int nt = 0; nt < 8; nt++) {
        float4 bv = wp[nt * 32];
        uint32_t bx = __float_as_uint(bv.x), by = __float_as_uint(bv.y);
        uint32_t bz = __float_as_uint(bv.z), bw = __float_as_uint(bv.w);
        mma8(acc[0][nt], a[0][0][0], a[0][0][1], a[0][0][2], a[0][0][3], bx, by);
        mma8(acc[1][nt], a[1][0][0], a[1][0][1], a[1][0][2], a[1][0][3], bx, by);
        mma8(acc[0][nt], a[0][1][0], a[0][1][1], a[0][1][2], a[0][1][3], bz, bw);
        mma8(acc[1][nt], a[1][1][0], a[1][1][1], a[1][1][2], a[1][1][3], bz, bw);
    }
}
__device__ __forceinline__ void layer2_direct(float (&acc)[2][8][4], char* smem,
        const float* __restrict__ Wfrag, int wm, int wn, int lid)
{
#pragma unroll
    for (int c = 0; c < 8; c++) {
        mma_frag_ldgW(acc, (const uint32_t*)(smem + OFF_A2) + c * 16, 132,
                      Wfrag + c * 2048, wm, wn, lid);
    }
}
template<bool ADDG>
__device__ __forceinline__ void epi1(float (&acc)[2][8][4], char* smem,
                                     int wm, int wn, int lid)
{
    float* A2 = (float*)(smem + OFF_A2);
    const float* be = (const float*)(smem + OFF_BE);
    const int g = lid >> 2, tg = lid & 3;
#pragma unroll
    for (int f = 0; f < 2; f++) {
        int r = wm * 32 + f * 16 + g;
#pragma unroll
        for (int nt = 0; nt < 8; nt++) {
            int n0 = wn * 64 + nt * 8 + tg * 2;
            float be0 = be[n0], be1 = be[n0 + 1];
            float g0x = 0.f, g0y = 0.f, g1x = 0.f, g1y = 0.f;
            if (ADDG) {
                float2 G0 = *(float2*)(A2 + r * 132 + n0);
                float2 G1 = *(float2*)(A2 + (r + 8) * 132 + n0);
                g0x = G0.x; g0y = G0.y; g1x = G1.x; g1y = G1.y;
            }
            float v0 = acc[f][nt][0] + be0 + g0x;
            float v1 = acc[f][nt][1] + be1 + g0y;
            float v2 = acc[f][nt][2] + be0 + g1x;
            float v3 = acc[f][nt][3] + be1 + g1y;
            v0 = (v0 > 0.f) ? v0 : expm1f(v0);
            v1 = (v1 > 0.f) ? v1 : expm1f(v1);
            v2 = (v2 > 0.f) ? v2 : expm1f(v2);
            v3 = (v3 > 0.f) ? v3 : expm1f(v3);
            *(float2*)(A2 + r * 132 + n0)       = make_float2(rtf(v0), rtf(v1));
            *(float2*)(A2 + (r + 8) * 132 + n0) = make_float2(rtf(v2), rtf(v3));
#pragma unroll
            for (int q = 0; q < 4; q++) acc[f][nt][q] = 0.f;
        }
    }
}
template<bool ROUND>
__device__ __forceinline__ void epi2(float (&acc)[2][8][4], char* smem,
                                     int wm, int wn, int lid)
{
    float* A2 = (float*)(smem + OFF_A2);
    const float* be = (const float*)(smem + OFF_B2V);
    const int g = lid >> 2, tg = lid & 3;
#pragma unroll
    for (int f = 0; f < 2; f++) {
        int r = wm * 32 + f * 16 + g;
#pragma unroll
        for (int nt = 0; nt < 8; nt++) {
            int n0 = wn * 64 + nt * 8 + tg * 2;
            float be0 = be[n0], be1 = be[n0 + 1];
            float v0 = acc[f][nt][0] + be0;
            float v1 = acc[f][nt][1] + be1;
            float v2 = acc[f][nt][2] + be0;
            float v3 = acc[f][nt][3] + be1;
            v0 = (v0 > 0.f) ? v0 : expm1f(v0);
            v1 = (v1 > 0.f) ? v1 : expm1f(v1);
            v2 = (v2 > 0.f) ? v2 : expm1f(v2);
            v3 = (v3 > 0.f) ? v3 : expm1f(v3);
            if (ROUND) { v0 = rtf(v0); v1 = rtf(v1); v2 = rtf(v2); v3 = rtf(v3); }
            *(float2*)(A2 + r * 132 + n0)       = make_float2(v0, v1);
            *(float2*)(A2 + (r + 8) * 132 + n0) = make_float2(v2, v3);
        }
    }
}
__device__ __forceinline__ void store_tile(char* smem, float* out, int row0, int tid,
                                           int ostride, int ocol)
{
    const float* A2 = (const float*)(smem + OFF_A2);
#pragma unroll
    for (int i = 0; i < 16; i++) {
        int idx4 = i * 256 + tid;
        int row = idx4 >> 5, c4 = idx4 & 31;
        float4 v = *(const float4*)(A2 + row * 132 + c4 * 4);
        *(float4*)(out + (size_t)(row0 + row) * ostride + ocol + c4 * 4) = v;
    }
}
__device__ __forceinline__ void stats_only(char* smem, int tid, int bx,
                                           float* psum, float* psq)
{
    if (tid >= 128) return;
    const float* A2 = (const float*)(smem + OFF_A2);
    float S = 0.f, Q = 0.f;
#pragma unroll 8
    for (int r = 0; r < 128; r++) {
        float x = A2[r * 132 + tid];
        S += x; Q += x * x;
    }
    psum[(size_t)bx * 128 + tid] = S;
    psq [(size_t)bx * 128 + tid] = Q;
}
#define ACC_DECL float acc[2][8][4]; \
    _Pragma("unroll") for (int f_ = 0; f_ < 2; f_++) \
    _Pragma("unroll") for (int n_ = 0; n_ < 8; n_++) \
    _Pragma("unroll") for (int q_ = 0; q_ < 4; q_++) acc[f_][n_][q_] = 0.f;

// =================== M=64 machinery (32x32 tiles, occ 3) ======================
#define PAIR_BAR128(wm) asm volatile("bar.sync %0, 128;" :: "r"(1 + (wm)) : "memory")
#define E_RECV   0
#define E_SEND   256
#define E_BE     512
#define E_B2V    1024
#define E_ACH    1536      /* 2 x 5120 A chunk buffers [64][20] */
#define E_A2     11776     /* 64 x 132 floats = 33792 */
#define E_SMEM   45568

__device__ __forceinline__ void mma_frag64(float (&acc)[2][4][4],
        const uint32_t* As, int AST, const float* __restrict__ Wchunk,
        int wm, int wn, int lid)
{
    const int g = lid >> 2, tg = lid & 3;
    float4 w[4];
    const float4* wp = (const float4*)Wchunk + wn * 128 + lid;
#pragma unroll
    for (int nt = 0; nt < 4; nt++) w[nt] = __ldg(wp + nt * 32);
    uint32_t a[2][2][4];
#pragma unroll
    for (int f = 0; f < 2; f++) {
        const uint32_t* p = As + (wm * 32 + f * 16 + g) * AST + tg;
#pragma unroll
        for (int ks = 0; ks < 2; ks++) {
            a[f][ks][0] = p[ks * 8];
            a[f][ks][1] = p[8 * AST + ks * 8];
            a[f][ks][2] = p[ks * 8 + 4];
            a[f][ks][3] = p[8 * AST + ks * 8 + 4];
        }
    }
#pragma unroll
    for (int nt = 0; nt < 4; nt++) {
        uint32_t bx = __float_as_uint(w[nt].x), by = __float_as_uint(w[nt].y);
        uint32_t bz = __float_as_uint(w[nt].z), bw = __float_as_uint(w[nt].w);
        mma8(acc[0][nt], a[0][0][0], a[0][0][1], a[0][0][2], a[0][0][3], bx, by);
        mma8(acc[1][nt], a[1][0][0], a[1][0][1], a[1][0][2], a[1][0][3], bx, by);
        mma8(acc[0][nt], a[0][1][0], a[0][1][1], a[0][1][2], a[0][1][3], bz, bw);
        mma8(acc[1][nt], a[1][1][0], a[1][1][1], a[1][1][2], a[1][1][3], bz, bw);
    }
}
// pair = 4 warps sharing wm (wid&1): 128 threads, pt = wn*32+lid
__device__ __forceinline__ void issue_a64(int c, int buf, uint32_t sb, int pt, int wm,
                                          const float* Asrc, int row0) {
    int row = wm * 32 + (pt >> 2), c4 = pt & 3;
    cp16(sb + E_ACH + buf * 5120 + row * 80 + c4 * 16,
         Asrc + (size_t)(row0 + row) * 128 + c * 16 + c4 * 4);
    asm volatile("cp.async.commit_group;");
}
__device__ __forceinline__ void layer1_64(float (&acc)[2][4][4], char* smem, uint32_t sb,
        const float* Asrc, int row0, const float* __restrict__ Wfrag,
        int wm, int wn, int lid, int pt, bool preissued)
{
    if (!preissued) {
        issue_a64(0, 0, sb, pt, wm, Asrc, row0);
        issue_a64(1, 1, sb, pt, wm, Asrc, row0);
    }
    for (int c = 0; c < 8; c++) {
        int buf = c & 1;
        if (c < 7) asm volatile("cp.async.wait_group 1;");
        else       asm volatile("cp.async.wait_group 0;");
        PAIR_BAR128(wm);
        mma_frag64(acc, (const uint32_t*)(smem + E_ACH + buf * 5120), 20,
                   Wfrag + c * 2048, wm, wn, lid);
        PAIR_BAR128(wm);
        if (c + 2 < 8) issue_a64(c + 2, buf, sb, pt, wm, Asrc, row0);
    }
}
__device__ __forceinline__ void layer2_64(float (&acc)[2][4][4], char* smem,
        const float* __restrict__ Wfrag, int wm, int wn, int lid)
{
#pragma unroll
    for (int c = 0; c < 8; c++) {
        mma_frag64(acc, (const uint32_t*)(smem + E_A2) + c * 16, 132,
                   Wfrag + c * 2048, wm, wn, lid);
    }
}
template<bool ADDG>
__device__ __forceinline__ void epi1_64(float (&acc)[2][4][4], char* smem,
                                        int wm, int wn, int lid)
{
    float* A2 = (float*)(smem + E_A2);
    const float* be = (const float*)(smem + E_BE);
    const int g = lid >> 2, tg = lid & 3;
#pragma unroll
    for (int f = 0; f < 2; f++) {
        int r = wm * 32 + f * 16 + g;
#pragma unroll
        for (int nt = 0; nt < 4; nt++) {
            int n0 = wn * 32 + nt * 8 + tg * 2;
            float be0 = be[n0], be1 = be[n0 + 1];
            float g0x = 0.f, g0y = 0.f, g1x = 0.f, g1y = 0.f;
            if (ADDG) {
                float2 G0 = *(float2*)(A2 + r * 132 + n0);
                float2 G1 = *(float2*)(A2 + (r + 8) * 132 + n0);
                g0x = G0.x; g0y = G0.y; g1x = G1.x; g1y = G1.y;
            }
            float v0 = acc[f][nt][0] + be0 + g0x;
            float v1 = acc[f][nt][1] + be1 + g0y;
            float v2 = acc[f][nt][2] + be0 + g1x;
            float v3 = acc[f][nt][3] + be1 + g1y;
            v0 = (v0 > 0.f) ? v0 : expm1f(v0);
            v1 = (v1 > 0.f) ? v1 : expm1f(v1);
            v2 = (v2 > 0.f) ? v2 : expm1f(v2);
            v3 = (v3 > 0.f) ? v3 : expm1f(v3);
            *(float2*)(A2 + r * 132 + n0)       = make_float2(rtf(v0), rtf(v1));
            *(float2*)(A2 + (r + 8) * 132 + n0) = make_float2(rtf(v2), rtf(v3));
#pragma unroll
            for (int q = 0; q < 4; q++) acc[f][nt][q] = 0.f;
        }
    }
}
template<bool ROUND>
__device__ __forceinline__ void epi2_64(float (&acc)[2][4][4], char* smem,
                                        int wm, int wn, int lid)
{
    float* A2 = (float*)(smem + E_A2);
    const float* be = (const float*)(smem + E_B2V);
    const int g = lid >> 2, tg = lid & 3;
#pragma unroll
    for (int f = 0; f < 2; f++) {
        int r = wm * 32 + f * 16 + g;
#pragma unroll
        for (int nt = 0; nt < 4; nt++) {
            int n0 = wn * 32 + nt * 8 + tg * 2;
            float be0 = be[n0], be1 = be[n0 + 1];
            float v0 = acc[f][nt][0] + be0;
            float v1 = acc[f][nt][1] + be1;
            float v2 = acc[f][nt][2] + be0;
            float v3 = acc[f][nt][3] + be1;
            v0 = (v0 > 0.f) ? v0 : expm1f(v0);
            v1 = (v1 > 0.f) ? v1 : expm1f(v1);
            v2 = (v2 > 0.f) ? v2 : expm1f(v2);
            v3 = (v3 > 0.f) ? v3 : expm1f(v3);
            if (ROUND) { v0 = rtf(v0); v1 = rtf(v1); v2 = rtf(v2); v3 = rtf(v3); }
            *(float2*)(A2 + r * 132 + n0)       = make_float2(v0, v1);
            *(float2*)(A2 + (r + 8) * 132 + n0) = make_float2(v2, v3);
        }
    }
}
__device__ __forceinline__ void store_tile64(char* smem, float* out, int row0, int tid,
                                             int ostride, int ocol)
{
    const float* A2 = (const float*)(smem + E_A2);
#pragma unroll
    for (int i = 0; i < 8; i++) {
        int idx4 = i * 256 + tid;
        int row = idx4 >> 5, c4 = idx4 & 31;
        float4 v = *(const float4*)(A2 + row * 132 + c4 * 4);
        *(float4*)(out + (size_t)(row0 + row) * ostride + ocol + c4 * 4) = v;
    }
}
// edge stats + node partials (channel-major psum)
__device__ __forceinline__ void stats64(char* smem, int row0, int tid, int bx,
        float* psum, float* psq, float* pnode)
{
    if (tid >= 128) return;
    const float* A2 = (const float*)(smem + E_A2);
    float S = 0.f, Q = 0.f, nacc = 0.f;
    int slot = 0;
    int nxt = 23 - (row0 % 23);
    float* pb = pnode + (size_t)bx * 4 * 128;
#pragma unroll 4
    for (int r = 0; r < 64; r++) {
        if (r == nxt) { pb[slot * 128 + tid] = nacc; slot++; nacc = 0.f; nxt += 23; }
        float x = A2[r * 132 + tid];
        S += x; Q += x * x; nacc += x;
    }
    pb[slot * 128 + tid] = nacc;
    psum[(size_t)tid * GE64 + bx] = S;
    psq [(size_t)tid * GE64 + bx] = Q;
}
// node stats (block-major psum), 64-row A2
__device__ __forceinline__ void stats_only64(char* smem, int tid, int bx,
                                             float* psum, float* psq)
{
    if (tid >= 128) return;
    const float* A2 = (const float*)(smem + E_A2);
    float S = 0.f, Q = 0.f;
#pragma unroll 8
    for (int r = 0; r < 64; r++) {
        float x = A2[r * 132 + tid];
        S += x; Q += x * x;
    }
    psum[(size_t)bx * 128 + tid] = S;
    psq [(size_t)bx * 128 + tid] = Q;
}
__device__ __forceinline__ void fill_edges64(char* smem, int row0, int tid) {
    if (tid < 64) {
        int row = row0 + tid;
        int b = row / NEDGE;
        int e = row - b * NEDGE;
        int r = e / 23;
        int j = e - r * 23;
        int s = j + (j >= r);
        ((int*)(smem + E_RECV))[tid] = b * NKPS + r;
        ((int*)(smem + E_SEND))[tid] = b * NKPS + s;
    }
}
#define ACC64_DECL float acc[2][4][4]; \
    _Pragma("unroll") for (int f_ = 0; f_ < 2; f_++) \
    _Pragma("unroll") for (int n_ = 0; n_ < 4; n_++) \
    _Pragma("unroll") for (int q_ = 0; q_ < 4; q_++) acc[f_][n_][q_] = 0.f;

// =================== kernels ==================================================
__global__ __launch_bounds__(256, 2)
void stage1_mlp(const float* __restrict__ X, const float* __restrict__ W1,
                const float* __restrict__ b1, const float* __restrict__ W2frag,
                const float* __restrict__ b2, float* __restrict__ out,
                float* __restrict__ psum, float* __restrict__ psq)
{
    extern __shared__ char smem[];
    const int tid = threadIdx.x, wid = tid >> 5, lid = tid & 31;
    const int wm = wid & 3, wn = wid >> 2;
    const int row0 = blockIdx.x * 128;
    float* smf = (float*)smem;
    if (tid < 128) { smf[OFF_BE/4 + tid] = b1[tid]; smf[OFF_B2V/4 + tid] = b2[tid]; }
#pragma unroll
    for (int i = 0; i < 8; i++) {
        int idx = i * 256 + tid;
        int row = idx >> 4, col = idx & 15;
        float av = (col < 6) ? X[(size_t)(row0 + row) * 6 + col] : 0.f;
        smf[OFF_ACH/4 + row * 20 + col] = rtf(av);
    }
#pragma unroll
    for (int i = 0; i < 8; i++) {
        int o = i * 256 + tid;
        int f4 = o >> 2, reg = o & 3;
        int nb = f4 >> 5, lane = f4 & 31, gg = lane >> 2, tg = lane & 3;
        int n = nb * 8 + gg;
        int k = (reg >> 1) * 8 + (reg & 1) * 4 + tg;
        smf[(OFF_ACH + 10240)/4 + o] = rtf((k < 6) ? W1[n * 6 + k] : 0.f);
    }
    __syncthreads();
    ACC_DECL
    mma_frag_smemW(acc, (const uint32_t*)(smem + OFF_ACH), 20,
                   (const float4*)(smem + OFF_ACH + 10240), wm, wn, lid);
    epi1<false>(acc, smem, wm, wn, lid);
    __syncthreads();
    layer2_direct(acc, smem, W2frag, wm, wn, lid);
    epi2<true>(acc, smem, wm, wn, lid);
    __syncthreads();
    store_tile(smem, out, row0, tid, 128, 0);
    stats_only(smem, tid, blockIdx.x, psum, psq);
}

// stage-3 node MLP with FUSED edge2node combine (M=64, occ 3)
__global__ __launch_bounds__(256, 3)
void node64_mlp(const float* __restrict__ pnode,
                const float* __restrict__ s2, const float* __restrict__ t2,
                const float* __restrict__ W1frag, const float* __restrict__ b1,
                const float* __restrict__ W2frag, const float* __restrict__ b2,
                float* __restrict__ out,
                float* __restrict__ psum, float* __restrict__ psq)
{
    extern __shared__ char smem[];
    const int tid = threadIdx.x, wid = tid >> 5, lid = tid & 31;
    const int wm = wid & 1, wn = wid >> 1;
    const int row0 = blockIdx.x * 64;
    float* smf = (float*)smem;
    if (tid < 128) { smf[E_BE/4 + tid] = b1[tid]; smf[E_B2V/4 + tid] = b2[tid]; }
    float* A2 = (float*)(smem + E_A2);
    // gather-combine: node2[row][c] = rtf((s2*sum + 23*t2)/24), identical to node_combine
#pragma unroll
    for (int i = 0; i < 32; i++) {
        int idx = i * 256 + tid;
        int row = idx >> 7, c = idx & 127;
        int n = row0 + row;
        int e0 = n * 23, e1 = e0 + 22;
        int b0 = e0 >> 6, b1e = e1 >> 6;
        int s0 = n - (b0 * 64) / 23;
        float sum = pnode[((size_t)b0 * 4 + s0) * 128 + c];
        if (b1e != b0) {
            int s1 = n - (b1e * 64) / 23;
            sum += pnode[((size_t)b1e * 4 + s1) * 128 + c];
        }
        A2[row * 132 + c] = rtf((__ldg(s2 + c) * sum + 23.f * __ldg(t2 + c)) * (1.f / 24.f));
    }
    __syncthreads();
    ACC64_DECL
    layer2_64(acc, smem, W1frag, wm, wn, lid);   // layer1: A resident in A2
    __syncthreads();                              // all warps done reading A2
    epi1_64<false>(acc, smem, wm, wn, lid);
    __syncthreads();
    layer2_64(acc, smem, W2frag, wm, wn, lid);
    epi2_64<true>(acc, smem, wm, wn, lid);
    __syncthreads();
    store_tile64(smem, out, row0, tid, 128, 0);
    stats_only64(smem, tid, blockIdx.x, psum, psq);
}

// PS[:, blk*128 : +128] = A @ Wfrag(blk)^T, raw fp32  (M=64 tiles, occ 3)
__global__ __launch_bounds__(256, 3)
void gemm_node(const float* __restrict__ A, const float* __restrict__ Wfrag,
               float* __restrict__ PS)
{
    extern __shared__ char smem[];
    const uint32_t sb = smem_u32(smem);
    const int tid = threadIdx.x, wid = tid >> 5, lid = tid & 31;
    const int wm = wid & 1, wn = wid >> 1;
    const int pt = wn * 32 + lid;
    const int row0 = blockIdx.x * 64;
    const int blk = blockIdx.y;
    ACC64_DECL
    layer1_64(acc, smem, sb, A, row0, Wfrag + (size_t)blk * 16384, wm, wn, lid, pt, false);
    float* A2 = (float*)(smem + E_A2);
    const int g = lid >> 2, tg = lid & 3;
#pragma unroll
    for (int f = 0; f < 2; f++) {
        int r = wm * 32 + f * 16 + g;
#pragma unroll
        for (int nt = 0; nt < 4; nt++) {
            int n0 = wn * 32 + nt * 8 + tg * 2;
            *(float2*)(A2 + r * 132 + n0)       = make_float2(acc[f][nt][0], acc[f][nt][1]);
            *(float2*)(A2 + (r + 8) * 132 + n0) = make_float2(acc[f][nt][2], acc[f][nt][3]);
        }
    }
    __syncthreads();
    store_tile64(smem, PS, row0, tid, 256, blk * 128);
}

// stage 2 edges (M=64, occ 3)
__global__ __launch_bounds__(256, 3)
void edge_stage2(const float* __restrict__ PS, const float* __restrict__ beff,
                 const float* __restrict__ W2frag, const float* __restrict__ b2,
                 float* __restrict__ out, float* __restrict__ psum, float* __restrict__ psq,
                 float* __restrict__ pnode)
{
    extern __shared__ char smem[];
    const int tid = threadIdx.x, wid = tid >> 5, lid = tid & 31;
    const int wm = wid & 1, wn = wid >> 1;
    const int row0 = blockIdx.x * 64;
    float* smf = (float*)smem;
    fill_edges64(smem, row0, tid);
    if (tid < 128) { smf[E_BE/4 + tid] = beff[tid]; smf[E_B2V/4 + tid] = b2[tid]; }
    __syncthreads();
    const int* rs = (const int*)(smem + E_RECV);
    const int* ss = (const int*)(smem + E_SEND);
    float* A2 = (float*)(smem + E_A2);
    const float* be = smf + E_BE/4;
#pragma unroll
    for (int i = 0; i < 8; i++) {
        int idx4 = i * 256 + tid;
        int row = idx4 >> 5, c4 = idx4 & 31;
        float4 p = *(const float4*)(PS + (size_t)rs[row] * 256 + c4 * 4);
        float4 s = *(const float4*)(PS + (size_t)ss[row] * 256 + 128 + c4 * 4);
        float v0 = p.x + s.x + be[c4 * 4];
        float v1 = p.y + s.y + be[c4 * 4 + 1];
        float v2 = p.z + s.z + be[c4 * 4 + 2];
        float v3 = p.w + s.w + be[c4 * 4 + 3];
        v0 = (v0 > 0.f) ? v0 : expm1f(v0);
        v1 = (v1 > 0.f) ? v1 : expm1f(v1);
        v2 = (v2 > 0.f) ? v2 : expm1f(v2);
        v3 = (v3 > 0.f) ? v3 : expm1f(v3);
        *(float4*)(A2 + row * 132 + c4 * 4) = make_float4(rtf(v0), rtf(v1), rtf(v2), rtf(v3));
    }
    __syncthreads();
    ACC64_DECL
    layer2_64(acc, smem, W2frag, wm, wn, lid);
    epi2_64<true>(acc, smem, wm, wn, lid);
    __syncthreads();
    store_tile64(smem, out, row0, tid, 128, 0);
    stats64(smem, row0, tid, blockIdx.x, psum, psq, pnode);
}

// stage 4 edges (M=64, occ 3)
__global__ __launch_bounds__(256, 3)
void edge_stage4(const float* __restrict__ PS3, const float* __restrict__ H2,
                 const float* __restrict__ SKIPfrag, const float* __restrict__ beff,
                 const float* __restrict__ W2frag, const float* __restrict__ b2,
                 float* __restrict__ psum, float* __restrict__ psq,
                 float* __restrict__ pnode)
{
    extern __shared__ char smem[];
    const uint32_t sb = smem_u32(smem);
    const int tid = threadIdx.x, wid = tid >> 5, lid = tid & 31;
    const int wm = wid & 1, wn = wid >> 1;
    const int pt = wn * 32 + lid;
    const int row0 = blockIdx.x * 64;
    float* smf = (float*)smem;
    fill_edges64(smem, row0, tid);
    if (tid < 128) { smf[E_BE/4 + tid] = beff[tid]; smf[E_B2V/4 + tid] = b2[tid]; }
    issue_a64(0, 0, sb, pt, wm, H2, row0);
    issue_a64(1, 1, sb, pt, wm, H2, row0);
    __syncthreads();
    const int* rs = (const int*)(smem + E_RECV);
    const int* ss = (const int*)(smem + E_SEND);
    float* A2 = (float*)(smem + E_A2);
#pragma unroll
    for (int i = 0; i < 8; i++) {
        int idx4 = i * 256 + tid;
        int row = idx4 >> 5, c4 = idx4 & 31;
        float4 p = *(const float4*)(PS3 + (size_t)rs[row] * 256 + c4 * 4);
        float4 s = *(const float4*)(PS3 + (size_t)ss[row] * 256 + 128 + c4 * 4);
        *(float4*)(A2 + row * 132 + c4 * 4) =
            make_float4(p.x + s.x, p.y + s.y, p.z + s.z, p.w + s.w);
    }
    ACC64_DECL
    layer1_64(acc, smem, sb, H2, row0, SKIPfrag, wm, wn, lid, pt, true);
    epi1_64<true>(acc, smem, wm, wn, lid);
    __syncthreads();
    layer2_64(acc, smem, W2frag, wm, wn, lid);
    epi2_64<false>(acc, smem, wm, wn, lid);
    __syncthreads();
    stats64(smem, row0, tid, blockIdx.x, psum, psq, pnode);
}

// ---- preps --------------------------------------------------------------------
__device__ __forceinline__ void frag_block(const float* W, int Kin, int kofs,
                                           const float* sv, float* dst, int o)
{
    int c = o >> 11, rem = o & 2047;
    int f4 = rem >> 2, reg = rem & 3;
    int nb = f4 >> 5, lane = f4 & 31;
    int g = lane >> 2, tg = lane & 3;
    int n = nb * 8 + g;
    int k = c * 16 + (reg >> 1) * 8 + (reg & 1) * 4 + tg;
    float v = W[(size_t)n * Kin + kofs + k];
    if (sv) v *= sv[k];
    dst[o] = __uint_as_float(f2tf(v));
}
__device__ __forceinline__ void bias_block(const float* W, int Kin, const float* b,
                                           const float* ta, const float* tb,
                                           float* beff, int n, int tid)
{
    float partial = 0.f;
    for (int k = tid; k < Kin; k += 256) {
        float t = (k < 256) ? ta[k & 127] : tb[k - 256];
        partial += W[(size_t)n * Kin + k] * t;
    }
    __shared__ float red[256];
    red[tid] = partial;
    __syncthreads();
    for (int off = 128; off; off >>= 1) {
        if (tid < off) red[tid] += red[tid + off];
        __syncthreads();
    }
    if (tid == 0) beff[n] = b[n] + red[0];
}
__device__ __forceinline__ void bn_inline(const float* psum, const float* psq, int nblk,
                                          float Minv, const float* g, const float* be,
                                          float* ss, float* st, int tid)
{
    if (tid < 128) {
        float S = 0.f, Q = 0.f;
        for (int i = 0; i < nblk; i++) {
            S += psum[i * 128 + tid];
            Q += psq [i * 128 + tid];
        }
        float mean = S * Minv;
        float var  = Q * Minv - mean * mean;
        float inv  = rsqrtf(var + BN_EPS);
        float sv   = g[tid] * inv;
        ss[tid] = sv;
        st[tid] = be[tid] - mean * sv;
    }
    __syncthreads();
}

__global__ void prep_indep(const float* W0, const float* W1, const float* W2,
                           const float* W3, const float* W4,
                           float* D0, float* D1, float* D2, float* D3, float* D4)
{
    int sel = blockIdx.x >> 6;
    int o = (blockIdx.x & 63) * 256 + threadIdx.x;
    const float* W = (sel == 0) ? W0 : (sel == 1) ? W1 : (sel == 2) ? W2
                   : (sel == 3) ? W3 : W4;
    float* D = (sel == 0) ? D0 : (sel == 1) ? D1 : (sel == 2) ? D2
             : (sel == 3) ? D3 : D4;
    frag_block(W, 128, 0, nullptr, D, o);
}
__global__ void prep_stage2(const float* __restrict__ W1, const float* __restrict__ b1,
                            const float* __restrict__ psum, const float* __restrict__ psq,
                            float Minv, const float* __restrict__ gg,
                            const float* __restrict__ gb,
                            float* __restrict__ psfrag, float* __restrict__ beff)
{
    __shared__ float ss[128], st[128];
    int bx = blockIdx.x, tid = threadIdx.x;
    bn_inline(psum, psq, GN_BLK, Minv, gg, gb, ss, st, tid);
    if (bx < 64)        frag_block(W1, 256, 0,   ss, psfrag,          bx * 256 + tid);
    else if (bx < 128)  frag_block(W1, 256, 128, ss, psfrag + 16384,  (bx - 64) * 256 + tid);
    else                bias_block(W1, 256, b1, st, nullptr, beff, bx - 128, tid);
}
__global__ void prep_stage4(const float* __restrict__ W1, const float* __restrict__ b1,
                            const float* __restrict__ psum, const float* __restrict__ psq,
                            float Minv, const float* __restrict__ gg,
                            const float* __restrict__ gb,
                            const float* __restrict__ s2, const float* __restrict__ t2,
                            float* __restrict__ psfrag, float* __restrict__ skipfrag,
                            float* __restrict__ beff)
{
    __shared__ float ss[128], st[128];
    int bx = blockIdx.x, tid = threadIdx.x;
    bn_inline(psum, psq, GN64, Minv, gg, gb, ss, st, tid);
    if (bx < 64)        frag_block(W1, 384, 0,   ss, psfrag,          bx * 256 + tid);
    else if (bx < 128)  frag_block(W1, 384, 128, ss, psfrag + 16384,  (bx - 64) * 256 + tid);
    else if (bx < 192)  frag_block(W1, 384, 256, s2, skipfrag,        (bx - 128) * 256 + tid);
    else                bias_block(W1, 384, b1, st, t2, beff, bx - 192, tid);
}

__global__ void bn_edge(const float* __restrict__ psum, const float* __restrict__ psq,
                        float Minv, const float* __restrict__ g, const float* __restrict__ be,
                        float* __restrict__ s, float* __restrict__ t)
{
    const int c = blockIdx.x, tid = threadIdx.x;
    float S = 0.f, Q = 0.f;
    for (int i = tid; i < GE64; i += 256) {
        S += psum[(size_t)c * GE64 + i];
        Q += psq [(size_t)c * GE64 + i];
    }
    __shared__ float rs[256], rq[256];
    rs[tid] = S; rq[tid] = Q;
    __syncthreads();
    for (int off = 128; off; off >>= 1) {
        if (tid < off) { rs[tid] += rs[tid + off]; rq[tid] += rq[tid + off]; }
        __syncthreads();
    }
    if (tid == 0) {
        float mean = rs[0] * Minv;
        float var  = rq[0] * Minv - mean * mean;
        float inv  = rsqrtf(var + BN_EPS);
        float sv   = g[c] * inv;
        s[c] = sv;
        t[c] = be[c] - mean * sv;
    }
}

__global__ void final_proj(const float* __restrict__ pnode,
                           const float* __restrict__ s, const float* __restrict__ t,
                           const float* __restrict__ fo_w, const float* __restrict__ fo_b,
                           float* __restrict__ out)
{
    int b = blockIdx.x;
    int c = threadIdx.x;
    float sc = s[c], tc = t[c];
    float a0 = 0.f, a1 = 0.f;
#pragma unroll
    for (int n = 0; n < NKPS; n++) {
        int nn = b * NKPS + n;
        int e0 = nn * 23, e1 = e0 + 22;
        int b0 = e0 >> 6, b1e = e1 >> 6;
        int s0 = nn - (b0 * 64) / 23;
        float sum = pnode[((size_t)b0 * 4 + s0) * 128 + c];
        if (b1e != b0) {
            int s1 = nn - (b1e * 64) / 23;
            sum += pnode[((size_t)b1e * 4 + s1) * 128 + c];
        }
        float v = (sc * sum + 23.f * tc) * (1.f / 24.f);
        a0 = fmaf(v, fo_w[n * 128 + c],        a0);
        a1 = fmaf(v, fo_w[3072 + n * 128 + c], a1);
    }
    __shared__ float r0[128], r1[128];
    r0[c] = a0; r1[c] = a1;
    __syncthreads();
    for (int off = 64; off; off >>= 1) {
        if (c < off) { r0[c] += r0[c + off]; r1[c] += r1[c + off]; }
        __syncthreads();
    }
    if (c == 0) {
        out[b * 2 + 0] = r0[0] + fo_b[0];
        out[b * 2 + 1] = r1[0] + fo_b[1];
    }
}

// ---- launch -------------------------------------------------------------------
extern "C" void kernel_launch(void* const* d_in, const int* in_sizes, int n_in,
                              void* d_out, int out_size)
{
    const float** I = (const float**)d_in;
    const float* inputs = I[0];
    const float *fo_w = I[3], *fo_b = I[4];
    const float *m1w1 = I[5],  *m1b1 = I[6],  *m1w2 = I[7],  *m1b2 = I[8],  *m1g = I[9],  *m1be = I[10];
    const float *m2w1 = I[11], *m2b1 = I[12], *m2w2 = I[13], *m2b2 = I[14], *m2g = I[15], *m2be = I[16];
    const float *m3w1 = I[17], *m3b1 = I[18], *m3w2 = I[19], *m3b2 = I[20], *m3g = I[21], *m3be = I[22];
    const float *m4w1 = I[23], *m4b1 = I[24], *m4w2 = I[25], *m4b2 = I[26], *m4g = I[27], *m4be = I[28];
    float* out = (float*)d_out;

    float *bufA, *n1, *n3, *ps, *pnode, *psfrag, *skipfrag, *w1f3;
    float *l2m1, *l2m2, *l2m3, *l2m4;
    float *beff, *psum, *psq, *sA, *tA;
    cudaGetSymbolAddress((void**)&bufA, g_bufA);
    cudaGetSymbolAddress((void**)&n1, g_n1);
    cudaGetSymbolAddress((void**)&n3, g_n3);
    cudaGetSymbolAddress((void**)&ps, g_ps);
    cudaGetSymbolAddress((void**)&pnode, g_pnode);
    cudaGetSymbolAddress((void**)&psfrag, g_psfrag);
    cudaGetSymbolAddress((void**)&skipfrag, g_skipfrag);
    cudaGetSymbolAddress((void**)&w1f3, g_w1f3);
    cudaGetSymbolAddress((void**)&l2m1, g_l2m1);
    cudaGetSymbolAddress((void**)&l2m2, g_l2m2);
    cudaGetSymbolAddress((void**)&l2m3, g_l2m3);
    cudaGetSymbolAddress((void**)&l2m4, g_l2m4);
    cudaGetSymbolAddress((void**)&beff, g_beff);
    cudaGetSymbolAddress((void**)&psum, g_psum);
    cudaGetSymbolAddress((void**)&psq, g_psq);
    cudaGetSymbolAddress((void**)&sA, g_s);
    cudaGetSymbolAddress((void**)&tA, g_t);

    cudaFuncSetAttribute(stage1_mlp,  cudaFuncAttributeMaxDynamicSharedMemorySize, SMEM_TOTAL);
    cudaFuncSetAttribute(node64_mlp,  cudaFuncAttributeMaxDynamicSharedMemorySize, E_SMEM);
    cudaFuncSetAttribute(gemm_node,   cudaFuncAttributeMaxDynamicSharedMemorySize, E_SMEM);
    cudaFuncSetAttribute(edge_stage2, cudaFuncAttributeMaxDynamicSharedMemorySize, E_SMEM);
    cudaFuncSetAttribute(edge_stage4, cudaFuncAttributeMaxDynamicSharedMemorySize, E_SMEM);

    const float MinvN = 1.0f / (float)M_NODE;
    const float MinvE = 1.0f / (float)M_EDGE;
    dim3 gnode(GN64, 2);

    // #1: all scale-independent weight frags
    prep_indep<<<320, 256>>>(m1w2, m2w2, m3w1, m3w2, m4w2,
                             l2m1, l2m2, w1f3, l2m3, l2m4);
    // #2: stage 1 (M=128)
    stage1_mlp<<<GN_BLK, 256, SMEM_TOTAL>>>(inputs, m1w1, m1b1, l2m1, m1b2, n1, psum, psq);
    // #3: stage-2 prep (BN1 fused, 192 stat blocks)
    prep_stage2<<<256, 256>>>(m2w1, m2b1, psum, psq, MinvN, m1g, m1be, psfrag, beff);
    // #4: node P/S GEMM (M=64, occ 3)  <-- profiled launch
    gemm_node<<<gnode, 256, E_SMEM>>>(n1, psfrag, ps);
    // #5: edges stage 2 (M=64, occ 3)
    edge_stage2<<<GE64, 256, E_SMEM>>>(ps, beff, l2m2, m2b2, bufA, psum, psq, pnode);
    // #6: BN2
    bn_edge<<<128, 256>>>(psum, psq, MinvE, m2g, m2be, sA + 128, tA + 128);
    // #7: stage 3 with FUSED combine (M=64, grid 384)
    node64_mlp<<<GN64, 256, E_SMEM>>>(pnode, sA + 128, tA + 128,
                                      w1f3, m3b1, l2m3, m3b2, n3, psum, psq);
    // #8: stage-4 prep (BN3 fused, 384 stat blocks)
    prep_stage4<<<320, 256>>>(m4w1, m4b1, psum, psq, MinvN, m3g, m3be,
                              sA + 128, tA + 128, psfrag, skipfrag, beff);
    // #9: node P/S GEMM for stage 4
    gemm_node<<<gnode, 256, E_SMEM>>>(n3, psfrag, ps);
    // #10: edges stage 4 (M=64, occ 3)
    edge_stage4<<<GE64, 256, E_SMEM>>>(ps, bufA, skipfrag, beff, l2m4, m4b2, psum, psq, pnode);
    // #11: BN4
    bn_edge<<<128, 256>>>(psum, psq, MinvE, m4g, m4be, sA + 384, tA + 384);
    // #12: final projection with fused combine
    final_proj<<<BATCH, 128>>>(pnode, sA + 384, tA + 384, fo_w, fo_b, out);
}